// round 2
// baseline (speedup 1.0000x reference)
#include <cuda_runtime.h>
#include <math.h>

#define NTOK 16384
#define CDIM 384
#define DI   768
#define LLEN 1024
#define NBAT 16
#define HIDD 1536
#define XZW  1536   // 2*DI

// ---------------- scratch (device globals: no allocation allowed) ----------------
__device__ float g_h1 [NTOK * CDIM];
__device__ float g_xz [NTOK * XZW];
__device__ float g_u  [NTOK * DI];
__device__ float g_xd [NTOK * 26];
__device__ float g_y  [NTOK * DI];
__device__ float g_g  [NTOK * DI];
__device__ float g_x1 [NTOK * CDIM];
__device__ float g_h2 [NTOK * CDIM];
__device__ float g_hid[NTOK * HIDD];

// ---------------- helpers ----------------
__device__ __forceinline__ float siluf(float x) { return x / (1.f + expf(-x)); }
__device__ __forceinline__ float geluf(float x) {
    // jax.nn.gelu default: tanh approximation
    float x3 = x * x * x;
    return 0.5f * x * (1.f + tanhf(0.7978845608028654f * (x + 0.044715f * x3)));
}
__device__ __forceinline__ float softplusf(float x) {
    return (x > 20.f) ? x : log1pf(expf(x));
}

// ---------------- LayerNorm (warp per row, float4 vectorized) ----------------
__global__ void ln_kernel(const float* __restrict__ x, const float* __restrict__ gam,
                          const float* __restrict__ bet, float* __restrict__ out,
                          int ncols, float eps)
{
    int row  = blockIdx.x * (blockDim.x >> 5) + (threadIdx.x >> 5);
    int lane = threadIdx.x & 31;
    const float4* x4 = (const float4*)(x + (size_t)row * ncols);
    int cnt = (ncols >> 2) >> 5;   // float4s per lane (3 for 384, 6 for 768)
    float4 v[6];
    float s = 0.f, s2 = 0.f;
    for (int i = 0; i < cnt; i++) {
        v[i] = x4[lane + (i << 5)];
        s  += v[i].x + v[i].y + v[i].z + v[i].w;
        s2 += v[i].x * v[i].x + v[i].y * v[i].y + v[i].z * v[i].z + v[i].w * v[i].w;
    }
    #pragma unroll
    for (int o = 16; o; o >>= 1) {
        s  += __shfl_xor_sync(0xffffffffu, s,  o);
        s2 += __shfl_xor_sync(0xffffffffu, s2, o);
    }
    float inv_n = 1.f / (float)ncols;
    float mu = s * inv_n;
    float var = fmaxf(s2 * inv_n - mu * mu, 0.f);
    float rstd = rsqrtf(var + eps);
    float4* o4 = (float4*)(out + (size_t)row * ncols);
    const float4* g4 = (const float4*)gam;
    const float4* b4 = (const float4*)bet;
    for (int i = 0; i < cnt; i++) {
        float4 gg = g4[lane + (i << 5)], bb = b4[lane + (i << 5)];
        float4 r;
        r.x = (v[i].x - mu) * rstd * gg.x + bb.x;
        r.y = (v[i].y - mu) * rstd * gg.y + bb.y;
        r.z = (v[i].z - mu) * rstd * gg.z + bb.z;
        r.w = (v[i].w - mu) * rstd * gg.w + bb.w;
        o4[lane + (i << 5)] = r;
    }
}

// ---------------- depthwise 3x3 conv (SAME) + silu, channels-last ----------------
__global__ void conv_silu_kernel(const float* __restrict__ xz,
                                 const float* __restrict__ cw,
                                 float* __restrict__ u)
{
    int t = blockIdx.x;
    int b = t >> 10, hw = t & 1023, h = hw >> 5, w = hw & 31;
    const float* base = xz + (size_t)(b << 10) * XZW;   // xm = first DI cols of xz
    for (int d = threadIdx.x; d < DI; d += blockDim.x) {
        float acc = 0.f;
        #pragma unroll
        for (int kh = 0; kh < 3; kh++) {
            int hh = h + kh - 1;
            if ((unsigned)hh >= 32u) continue;
            #pragma unroll
            for (int kw = 0; kw < 3; kw++) {
                int ww = w + kw - 1;
                if ((unsigned)ww >= 32u) continue;
                acc = fmaf(base[(size_t)(hh * 32 + ww) * XZW + d],
                           cw[d * 9 + kh * 3 + kw], acc);
            }
        }
        u[(size_t)t * DI + d] = siluf(acc);
    }
}

// ---------------- x_dbl = u @ x_proj_w  (warp per token, 26 outputs) ----------------
__global__ void xdbl_kernel(const float* __restrict__ u, const float* __restrict__ W,
                            float* __restrict__ xd)
{
    int t    = blockIdx.x * (blockDim.x >> 5) + (threadIdx.x >> 5);
    int lane = threadIdx.x & 31;
    const float* ur = u + (size_t)t * DI;
    float uc[24];
    #pragma unroll
    for (int i = 0; i < 24; i++) uc[i] = ur[lane + 32 * i];
    for (int k = 0; k < 26; k++) {
        float s = 0.f;
        #pragma unroll
        for (int i = 0; i < 24; i++)
            s = fmaf(uc[i], W[(size_t)(lane + 32 * i) * 26 + k], s);
        #pragma unroll
        for (int o = 16; o; o >>= 1) s += __shfl_xor_sync(0xffffffffu, s, o);
        if (lane == 0) xd[(size_t)t * 26 + k] = s;
    }
}

// --------- fused dt_proj + softplus + selective scan (DS=1) + y epilogue ---------
// warp handles 32 channels of one batch, sequential over L (raster order).
__global__ void scan_kernel(const float* __restrict__ u, const float* __restrict__ xd,
                            const float* __restrict__ dtw, const float* __restrict__ dtb,
                            const float* __restrict__ A_log, const float* __restrict__ Dp,
                            float* __restrict__ y)
{
    int gwarp = (blockIdx.x * blockDim.x + threadIdx.x) >> 5;   // 0..383
    int lane  = threadIdx.x & 31;
    int b = gwarp / (DI / 32);
    int d = (gwarp % (DI / 32)) * 32 + lane;

    float Wdt[24];
    #pragma unroll
    for (int r = 0; r < 24; r++) Wdt[r] = dtw[r * DI + d];
    float bias = dtb[d];
    float Aval = -expf(A_log[d]);
    float Dval = Dp[d];

    const float* up = u  + (size_t)b * LLEN * DI + d;
    const float* xp = xd + (size_t)b * LLEN * 26;
    float*       yp = y  + (size_t)b * LLEN * DI + d;

    float h = 0.f;
    float xval = (lane < 26) ? xp[lane] : 0.f;
    float uv   = up[0];
    for (int l = 0; l < LLEN; l++) {
        // prefetch next iteration (independent of recurrence)
        float xn = 0.f, un = 0.f;
        if (l + 1 < LLEN) {
            xn = (lane < 26) ? xp[(l + 1) * 26 + lane] : 0.f;
            un = up[(size_t)(l + 1) * DI];
        }
        float dtv = bias;
        #pragma unroll
        for (int r = 0; r < 24; r++)
            dtv = fmaf(__shfl_sync(0xffffffffu, xval, r), Wdt[r], dtv);
        float Bc = __shfl_sync(0xffffffffu, xval, 24);
        float Cc = __shfl_sync(0xffffffffu, xval, 25);
        dtv = softplusf(dtv);
        float dA = expf(dtv * Aval);
        h = fmaf(dA, h, dtv * Bc * uv);
        yp[(size_t)l * DI] = fmaf(h, Cc, uv * Dval);
        xval = xn; uv = un;
    }
}

// ------------- out-norm (eps 1e-5) over DI + gating with silu(z) -------------
__global__ void lngate_kernel(const float* __restrict__ y, const float* __restrict__ xz,
                              const float* __restrict__ gam, const float* __restrict__ bet,
                              float* __restrict__ out)
{
    int t    = blockIdx.x * (blockDim.x >> 5) + (threadIdx.x >> 5);
    int lane = threadIdx.x & 31;
    const float4* y4 = (const float4*)(y + (size_t)t * DI);
    float4 v[6];
    float s = 0.f, s2 = 0.f;
    #pragma unroll
    for (int i = 0; i < 6; i++) {
        v[i] = y4[lane + (i << 5)];
        s  += v[i].x + v[i].y + v[i].z + v[i].w;
        s2 += v[i].x * v[i].x + v[i].y * v[i].y + v[i].z * v[i].z + v[i].w * v[i].w;
    }
    #pragma unroll
    for (int o = 16; o; o >>= 1) {
        s  += __shfl_xor_sync(0xffffffffu, s,  o);
        s2 += __shfl_xor_sync(0xffffffffu, s2, o);
    }
    float mu = s * (1.f / DI);
    float rstd = rsqrtf(fmaxf(s2 * (1.f / DI) - mu * mu, 0.f) + 1e-5f);
    const float4* z4 = (const float4*)(xz + (size_t)t * XZW + DI);
    const float4* g4 = (const float4*)gam;
    const float4* b4 = (const float4*)bet;
    float4* o4 = (float4*)(out + (size_t)t * DI);
    #pragma unroll
    for (int i = 0; i < 6; i++) {
        float4 zz = z4[lane + (i << 5)];
        float4 gg = g4[lane + (i << 5)], bb = b4[lane + (i << 5)];
        float4 r;
        r.x = ((v[i].x - mu) * rstd * gg.x + bb.x) * siluf(zz.x);
        r.y = ((v[i].y - mu) * rstd * gg.y + bb.y) * siluf(zz.y);
        r.z = ((v[i].z - mu) * rstd * gg.z + bb.z) * siluf(zz.z);
        r.w = ((v[i].w - mu) * rstd * gg.w + bb.w) * siluf(zz.w);
        o4[lane + (i << 5)] = r;
    }
}

// ---------------- SGEMM: C = A(MxK) @ B(KxN) [+bias][+gelu][+resid] ----------------
// MODE: 0 plain, 1 bias+gelu, 2 bias+resid, 3 resid
#define BM 128
#define BN 64
#define BK 16
#define TM 8
#define TN 4

template <int MODE>
__global__ void __launch_bounds__(256, 2)
sgemm(const float* __restrict__ A, const float* __restrict__ Bm,
      float* __restrict__ C, int M, int N, int K,
      const float* __restrict__ bias, const float* __restrict__ resid)
{
    __shared__ float As[BK][BM];
    __shared__ float Bs[BK][BN];
    int bm = blockIdx.y * BM, bn = blockIdx.x * BN;
    int tid = threadIdx.x;
    int tr = tid >> 4, tc = tid & 15;   // 16x16 thread grid

    float acc[TM][TN];
    #pragma unroll
    for (int i = 0; i < TM; i++)
        #pragma unroll
        for (int j = 0; j < TN; j++) acc[i][j] = 0.f;

    for (int k0 = 0; k0 < K; k0 += BK) {
        // load A tile (BM x BK) transposed into smem: 512 float4, 2 per thread
        #pragma unroll
        for (int i = 0; i < 2; i++) {
            int f = tid + i * 256;
            int r = f >> 2, kc = (f & 3) << 2;
            float4 va = *(const float4*)(A + (size_t)(bm + r) * K + k0 + kc);
            As[kc + 0][r] = va.x; As[kc + 1][r] = va.y;
            As[kc + 2][r] = va.z; As[kc + 3][r] = va.w;
        }
        // load B tile (BK x BN): 256 float4, 1 per thread
        {
            int r = tid >> 4, c = (tid & 15) << 2;
            *(float4*)&Bs[r][c] = *(const float4*)(Bm + (size_t)(k0 + r) * N + bn + c);
        }
        __syncthreads();
        #pragma unroll
        for (int kk = 0; kk < BK; kk++) {
            float4 a0 = *(const float4*)&As[kk][tr * TM];
            float4 a1 = *(const float4*)&As[kk][tr * TM + 4];
            float4 bf = *(const float4*)&Bs[kk][tc * TN];
            float av[TM] = {a0.x, a0.y, a0.z, a0.w, a1.x, a1.y, a1.z, a1.w};
            float bv[TN] = {bf.x, bf.y, bf.z, bf.w};
            #pragma unroll
            for (int i = 0; i < TM; i++)
                #pragma unroll
                for (int j = 0; j < TN; j++)
                    acc[i][j] = fmaf(av[i], bv[j], acc[i][j]);
        }
        __syncthreads();
    }

    int col0 = bn + tc * TN;
    float4 bfrag = make_float4(0.f, 0.f, 0.f, 0.f);
    if (MODE == 1 || MODE == 2) bfrag = *(const float4*)(bias + col0);
    #pragma unroll
    for (int i = 0; i < TM; i++) {
        int row = bm + tr * TM + i;
        float4 r = make_float4(acc[i][0], acc[i][1], acc[i][2], acc[i][3]);
        if (MODE == 1) {
            r.x = geluf(r.x + bfrag.x); r.y = geluf(r.y + bfrag.y);
            r.z = geluf(r.z + bfrag.z); r.w = geluf(r.w + bfrag.w);
        } else if (MODE == 2) {
            float4 rs = *(const float4*)(resid + (size_t)row * N + col0);
            r.x += bfrag.x + rs.x; r.y += bfrag.y + rs.y;
            r.z += bfrag.z + rs.z; r.w += bfrag.w + rs.w;
        } else if (MODE == 3) {
            float4 rs = *(const float4*)(resid + (size_t)row * N + col0);
            r.x += rs.x; r.y += rs.y; r.z += rs.z; r.w += rs.w;
        }
        *(float4*)(C + (size_t)row * N + col0) = r;
    }
}

// ---------------- launch ----------------
extern "C" void kernel_launch(void* const* d_in, const int* in_sizes, int n_in,
                              void* d_out, int out_size)
{
    const float* x        = (const float*)d_in[0];
    const float* ln1_g    = (const float*)d_in[1];
    const float* ln1_b    = (const float*)d_in[2];
    const float* w_in     = (const float*)d_in[3];
    const float* conv_w   = (const float*)d_in[4];
    const float* x_proj_w = (const float*)d_in[5];
    const float* dt_w     = (const float*)d_in[6];
    const float* dt_b     = (const float*)d_in[7];
    const float* A_log    = (const float*)d_in[8];
    const float* Dp       = (const float*)d_in[9];
    const float* on_g     = (const float*)d_in[10];
    const float* on_b     = (const float*)d_in[11];
    const float* w_out    = (const float*)d_in[12];
    const float* ln2_g    = (const float*)d_in[13];
    const float* ln2_b    = (const float*)d_in[14];
    const float* fc1_w    = (const float*)d_in[15];
    const float* fc1_b    = (const float*)d_in[16];
    const float* fc2_w    = (const float*)d_in[17];
    const float* fc2_b    = (const float*)d_in[18];
    float* out = (float*)d_out;

    float *h1, *xz, *u, *xd, *y, *g, *x1, *h2, *hid;
    cudaGetSymbolAddress((void**)&h1,  g_h1);
    cudaGetSymbolAddress((void**)&xz,  g_xz);
    cudaGetSymbolAddress((void**)&u,   g_u);
    cudaGetSymbolAddress((void**)&xd,  g_xd);
    cudaGetSymbolAddress((void**)&y,   g_y);
    cudaGetSymbolAddress((void**)&g,   g_g);
    cudaGetSymbolAddress((void**)&x1,  g_x1);
    cudaGetSymbolAddress((void**)&h2,  g_h2);
    cudaGetSymbolAddress((void**)&hid, g_hid);

    // 1. h1 = LN(x)   (eps 1e-6)
    ln_kernel<<<NTOK / 8, 256>>>(x, ln1_g, ln1_b, h1, CDIM, 1e-6f);
    // 2. xz = h1 @ w_in   (16384 x 1536, K=384)
    sgemm<0><<<dim3(XZW / BN, NTOK / BM), 256>>>(h1, w_in, xz, NTOK, XZW, CDIM, nullptr, nullptr);
    // 3. u = silu(dwconv3x3(xm))
    conv_silu_kernel<<<NTOK, 256>>>(xz, conv_w, u);
    // 4. x_dbl = u @ x_proj_w   (16384 x 26, K=768)
    xdbl_kernel<<<NTOK / 8, 256>>>(u, x_proj_w, xd);
    // 5. fused dt_proj + softplus + selective scan + y
    scan_kernel<<<(NBAT * (DI / 32) * 32) / 256, 256>>>(u, xd, dt_w, dt_b, A_log, Dp, y);
    // 6. g = LN_out(y) * silu(z)   (eps 1e-5)
    lngate_kernel<<<NTOK / 8, 256>>>(y, xz, on_g, on_b, g);
    // 7. x1 = g @ w_out + x   (16384 x 384, K=768)
    sgemm<3><<<dim3(CDIM / BN, NTOK / BM), 256>>>(g, w_out, x1, NTOK, CDIM, DI, nullptr, x);
    // 8. h2 = LN(x1)   (eps 1e-6)
    ln_kernel<<<NTOK / 8, 256>>>(x1, ln2_g, ln2_b, h2, CDIM, 1e-6f);
    // 9. hid = gelu(h2 @ fc1_w + fc1_b)   (16384 x 1536, K=384)
    sgemm<1><<<dim3(HIDD / BN, NTOK / BM), 256>>>(h2, fc1_w, hid, NTOK, HIDD, CDIM, fc1_b, nullptr);
    // 10. out = hid @ fc2_w + fc2_b + x1   (16384 x 384, K=1536)
    sgemm<2><<<dim3(CDIM / BN, NTOK / BM), 256>>>(hid, fc2_w, out, NTOK, CDIM, HIDD, fc2_b, x1);
}

// round 3
// speedup vs baseline: 1.8548x; 1.8548x over previous
#include <cuda_runtime.h>
#include <math.h>
#include <stdint.h>

#define NTOK 16384
#define CDIM 384
#define DI   768
#define LLEN 1024
#define NBAT 16
#define HIDD 1536
#define XZW  1536   // 2*DI

// ---------------- scratch (device globals: no allocation allowed) ----------------
__device__ float g_h1 [NTOK * CDIM];
__device__ float g_xz [NTOK * XZW];
__device__ float g_u  [NTOK * DI];
__device__ float g_xd [NTOK * 26];
__device__ float g_dt [NTOK * DI];
__device__ float g_y  [NTOK * DI];
__device__ float g_g  [NTOK * DI];
__device__ float g_x1 [NTOK * CDIM];
__device__ float g_h2 [NTOK * CDIM];
__device__ float g_hid[NTOK * HIDD];

// ---------------- helpers ----------------
__device__ __forceinline__ float siluf(float x) { return x / (1.f + expf(-x)); }
__device__ __forceinline__ float geluf(float x) {
    float x3 = x * x * x;
    return 0.5f * x * (1.f + tanhf(0.7978845608028654f * (x + 0.044715f * x3)));
}
__device__ __forceinline__ float softplusf(float x) {
    return (x > 20.f) ? x : log1pf(expf(x));
}
__device__ __forceinline__ float totf32(float x) {
    uint32_t o;
    asm("cvt.rna.tf32.f32 %0, %1;" : "=r"(o) : "f"(x));
    return __uint_as_float(o);
}
__device__ __forceinline__ void mma_tf32(float* d, const uint32_t* a, const uint32_t* b) {
    asm volatile(
        "mma.sync.aligned.m16n8k8.row.col.f32.tf32.tf32.f32 "
        "{%0,%1,%2,%3}, {%4,%5,%6,%7}, {%8,%9}, {%0,%1,%2,%3};"
        : "+f"(d[0]), "+f"(d[1]), "+f"(d[2]), "+f"(d[3])
        : "r"(a[0]), "r"(a[1]), "r"(a[2]), "r"(a[3]), "r"(b[0]), "r"(b[1]));
}

// ---------------- LayerNorm (warp per row, float4 vectorized) ----------------
__global__ void ln_kernel(const float* __restrict__ x, const float* __restrict__ gam,
                          const float* __restrict__ bet, float* __restrict__ out,
                          int ncols, float eps)
{
    int row  = blockIdx.x * (blockDim.x >> 5) + (threadIdx.x >> 5);
    int lane = threadIdx.x & 31;
    const float4* x4 = (const float4*)(x + (size_t)row * ncols);
    int cnt = (ncols >> 2) >> 5;
    float4 v[6];
    float s = 0.f, s2 = 0.f;
    for (int i = 0; i < cnt; i++) {
        v[i] = x4[lane + (i << 5)];
        s  += v[i].x + v[i].y + v[i].z + v[i].w;
        s2 += v[i].x * v[i].x + v[i].y * v[i].y + v[i].z * v[i].z + v[i].w * v[i].w;
    }
    #pragma unroll
    for (int o = 16; o; o >>= 1) {
        s  += __shfl_xor_sync(0xffffffffu, s,  o);
        s2 += __shfl_xor_sync(0xffffffffu, s2, o);
    }
    float inv_n = 1.f / (float)ncols;
    float mu = s * inv_n;
    float var = fmaxf(s2 * inv_n - mu * mu, 0.f);
    float rstd = rsqrtf(var + eps);
    float4* o4 = (float4*)(out + (size_t)row * ncols);
    const float4* g4 = (const float4*)gam;
    const float4* b4 = (const float4*)bet;
    for (int i = 0; i < cnt; i++) {
        float4 gg = g4[lane + (i << 5)], bb = b4[lane + (i << 5)];
        float4 r;
        r.x = (v[i].x - mu) * rstd * gg.x + bb.x;
        r.y = (v[i].y - mu) * rstd * gg.y + bb.y;
        r.z = (v[i].z - mu) * rstd * gg.z + bb.z;
        r.w = (v[i].w - mu) * rstd * gg.w + bb.w;
        o4[lane + (i << 5)] = r;
    }
}

// ---------------- depthwise 3x3 conv (SAME) + silu ----------------
__global__ void conv_silu_kernel(const float* __restrict__ xz,
                                 const float* __restrict__ cw,
                                 float* __restrict__ u)
{
    int t = blockIdx.x;
    int b = t >> 10, hw = t & 1023, h = hw >> 5, w = hw & 31;
    const float* base = xz + (size_t)(b << 10) * XZW;
    for (int d = threadIdx.x; d < DI; d += blockDim.x) {
        float acc = 0.f;
        #pragma unroll
        for (int kh = 0; kh < 3; kh++) {
            int hh = h + kh - 1;
            if ((unsigned)hh >= 32u) continue;
            #pragma unroll
            for (int kw = 0; kw < 3; kw++) {
                int ww = w + kw - 1;
                if ((unsigned)ww >= 32u) continue;
                acc = fmaf(base[(size_t)(hh * 32 + ww) * XZW + d],
                           cw[d * 9 + kh * 3 + kw], acc);
            }
        }
        u[(size_t)t * DI + d] = siluf(acc);
    }
}

// ------------- x_dbl = u @ x_proj_w, W^T cached in smem, 128 tokens/block -------------
__global__ void xdbl_kernel(const float* __restrict__ u, const float* __restrict__ W,
                            float* __restrict__ xd)
{
    extern __shared__ float sW[];   // [26][768]
    int tid = threadIdx.x;
    for (int i = tid; i < 26 * DI; i += 256) {
        int k = i / DI, d = i - k * DI;
        sW[i] = W[(size_t)d * 26 + k];
    }
    __syncthreads();
    int warp = tid >> 5, lane = tid & 31;
    int tok0 = blockIdx.x * 128 + warp;
    for (int rep = 0; rep < 16; rep++) {
        int tok = tok0 + rep * 8;
        const float* ur = u + (size_t)tok * DI;
        float uc[24];
        #pragma unroll
        for (int i = 0; i < 24; i++) uc[i] = ur[lane + 32 * i];
        #pragma unroll 2
        for (int k = 0; k < 26; k++) {
            float s = 0.f;
            const float* wr = sW + k * DI;
            #pragma unroll
            for (int i = 0; i < 24; i++)
                s = fmaf(uc[i], wr[lane + 32 * i], s);
            #pragma unroll
            for (int o = 16; o; o >>= 1) s += __shfl_xor_sync(0xffffffffu, s, o);
            if (lane == 0) xd[(size_t)tok * 26 + k] = s;
        }
    }
}

// ------------- dt = softplus(xd[:, :24] @ dt_proj_w + b), parallel -------------
__global__ void dt_kernel(const float* __restrict__ xd, const float* __restrict__ dtw,
                          const float* __restrict__ dtb, float* __restrict__ dto)
{
    int d   = blockIdx.x * 256 + threadIdx.x;   // 0..767
    int tok = blockIdx.y;
    const float* xr = xd + (size_t)tok * 26;
    float s = dtb[d];
    #pragma unroll
    for (int r = 0; r < 24; r++)
        s = fmaf(xr[r], dtw[(size_t)r * DI + d], s);
    dto[(size_t)tok * DI + d] = softplusf(s);
}

// --------- selective scan (DS=1) + y epilogue: pure recurrence, prefetch ---------
__global__ void scan_kernel(const float* __restrict__ u, const float* __restrict__ dt,
                            const float* __restrict__ xd,
                            const float* __restrict__ A_log, const float* __restrict__ Dp,
                            float* __restrict__ y)
{
    int gwarp = (blockIdx.x * blockDim.x + threadIdx.x) >> 5;
    int lane  = threadIdx.x & 31;
    int b = gwarp / (DI / 32);
    int d = (gwarp % (DI / 32)) * 32 + lane;

    float Aval = -expf(A_log[d]);
    float Dval = Dp[d];

    const float* up = u  + (size_t)b * LLEN * DI + d;
    const float* dp = dt + (size_t)b * LLEN * DI + d;
    const float* xp = xd + (size_t)b * LLEN * 26;
    float*       yp = y  + (size_t)b * LLEN * DI + d;

    float h = 0.f;
    float uv = up[0], dtv = dp[0], Bc = xp[24], Cc = xp[25];
    for (int l = 0; l < LLEN; l++) {
        float un = 0.f, dn = 0.f, Bn = 0.f, Cn = 0.f;
        if (l + 1 < LLEN) {
            un = up[(size_t)(l + 1) * DI];
            dn = dp[(size_t)(l + 1) * DI];
            Bn = xp[(l + 1) * 26 + 24];
            Cn = xp[(l + 1) * 26 + 25];
        }
        float dA = expf(dtv * Aval);
        h = fmaf(dA, h, dtv * Bc * uv);
        yp[(size_t)l * DI] = fmaf(h, Cc, uv * Dval);
        uv = un; dtv = dn; Bc = Bn; Cc = Cn;
    }
}

// ------------- out-norm (eps 1e-5) over DI + gating with silu(z) -------------
__global__ void lngate_kernel(const float* __restrict__ y, const float* __restrict__ xz,
                              const float* __restrict__ gam, const float* __restrict__ bet,
                              float* __restrict__ out)
{
    int t    = blockIdx.x * (blockDim.x >> 5) + (threadIdx.x >> 5);
    int lane = threadIdx.x & 31;
    const float4* y4 = (const float4*)(y + (size_t)t * DI);
    float4 v[6];
    float s = 0.f, s2 = 0.f;
    #pragma unroll
    for (int i = 0; i < 6; i++) {
        v[i] = y4[lane + (i << 5)];
        s  += v[i].x + v[i].y + v[i].z + v[i].w;
        s2 += v[i].x * v[i].x + v[i].y * v[i].y + v[i].z * v[i].z + v[i].w * v[i].w;
    }
    #pragma unroll
    for (int o = 16; o; o >>= 1) {
        s  += __shfl_xor_sync(0xffffffffu, s,  o);
        s2 += __shfl_xor_sync(0xffffffffu, s2, o);
    }
    float mu = s * (1.f / DI);
    float rstd = rsqrtf(fmaxf(s2 * (1.f / DI) - mu * mu, 0.f) + 1e-5f);
    const float4* z4 = (const float4*)(xz + (size_t)t * XZW + DI);
    const float4* g4 = (const float4*)gam;
    const float4* b4 = (const float4*)bet;
    float4* o4 = (float4*)(out + (size_t)t * DI);
    #pragma unroll
    for (int i = 0; i < 6; i++) {
        float4 zz = z4[lane + (i << 5)];
        float4 gg = g4[lane + (i << 5)], bb = b4[lane + (i << 5)];
        float4 r;
        r.x = ((v[i].x - mu) * rstd * gg.x + bb.x) * siluf(zz.x);
        r.y = ((v[i].y - mu) * rstd * gg.y + bb.y) * siluf(zz.y);
        r.z = ((v[i].z - mu) * rstd * gg.z + bb.z) * siluf(zz.z);
        r.w = ((v[i].w - mu) * rstd * gg.w + bb.w) * siluf(zz.w);
        o4[lane + (i << 5)] = r;
    }
}

// ---------------- TF32 tensor-core GEMM: C = A(MxK) @ B(KxN) ----------------
// MODE: 0 plain, 1 bias+gelu, 2 bias+resid, 3 resid
#define GBM 128
#define GBN 128
#define GBK 32
#define AS_STRIDE 36     // GBK+4
#define BS_STRIDE 136    // GBN+8
#define AS_STAGE  (GBM * AS_STRIDE)   // 4608 floats
#define BS_STAGE  (GBK * BS_STRIDE)   // 4352 floats
#define GEMM_SMEM ((2 * AS_STAGE + 2 * BS_STAGE) * 4)   // 71680 bytes

template <int MODE>
__global__ void __launch_bounds__(256)
gemm_tc(const float* __restrict__ A, const float* __restrict__ Bm,
        float* __restrict__ C, int M, int N, int K,
        const float* __restrict__ bias, const float* __restrict__ resid)
{
    extern __shared__ float sm[];
    float* As = sm;                   // [2][GBM][AS_STRIDE]
    float* Bs = sm + 2 * AS_STAGE;    // [2][GBK][BS_STRIDE]

    int bm = blockIdx.y * GBM, bn = blockIdx.x * GBN;
    int tid = threadIdx.x;
    int warp = tid >> 5, lane = tid & 31;
    int wm = warp >> 2, wn = warp & 3;     // 2x4 warp grid: 64x32 per warp
    int g = lane >> 2, t = lane & 3;

    float acc[4][4][4];
    #pragma unroll
    for (int i = 0; i < 4; i++)
        #pragma unroll
        for (int j = 0; j < 4; j++)
            #pragma unroll
            for (int r = 0; r < 4; r++) acc[i][j][r] = 0.f;

    float4 pa[4], pb[4];
    int ar[4], ac[4], br[4], bc[4];
    #pragma unroll
    for (int i = 0; i < 4; i++) {
        int f = tid + i * 256;
        ar[i] = f >> 3; ac[i] = (f & 7) << 2;
        br[i] = f >> 5; bc[i] = (f & 31) << 2;
    }

    // prologue: load stage 0
    #pragma unroll
    for (int i = 0; i < 4; i++) {
        pa[i] = *(const float4*)(A + (size_t)(bm + ar[i]) * K + ac[i]);
        pb[i] = *(const float4*)(Bm + (size_t)br[i] * N + bn + bc[i]);
    }
    #pragma unroll
    for (int i = 0; i < 4; i++) {
        float* a = &As[ar[i] * AS_STRIDE + ac[i]];
        a[0] = totf32(pa[i].x); a[1] = totf32(pa[i].y);
        a[2] = totf32(pa[i].z); a[3] = totf32(pa[i].w);
        float* bsp = &Bs[br[i] * BS_STRIDE + bc[i]];
        bsp[0] = totf32(pb[i].x); bsp[1] = totf32(pb[i].y);
        bsp[2] = totf32(pb[i].z); bsp[3] = totf32(pb[i].w);
    }
    __syncthreads();

    int nIter = K / GBK;
    for (int it = 0; it < nIter; it++) {
        int buf = it & 1;
        // prefetch next tile to registers
        if (it + 1 < nIter) {
            int k0 = (it + 1) * GBK;
            #pragma unroll
            for (int i = 0; i < 4; i++) {
                pa[i] = *(const float4*)(A + (size_t)(bm + ar[i]) * K + k0 + ac[i]);
                pb[i] = *(const float4*)(Bm + (size_t)(k0 + br[i]) * N + bn + bc[i]);
            }
        }
        // compute on smem[buf]
        const float* Ab = As + buf * AS_STAGE;
        const float* Bb = Bs + buf * BS_STAGE;
        #pragma unroll
        for (int ks = 0; ks < 4; ks++) {
            int kb = ks * 8;
            uint32_t af[4][4], bf[4][2];
            #pragma unroll
            for (int mi = 0; mi < 4; mi++) {
                int r0 = wm * 64 + mi * 16 + g;
                af[mi][0] = __float_as_uint(Ab[(r0    ) * AS_STRIDE + kb + t    ]);
                af[mi][1] = __float_as_uint(Ab[(r0 + 8) * AS_STRIDE + kb + t    ]);
                af[mi][2] = __float_as_uint(Ab[(r0    ) * AS_STRIDE + kb + t + 4]);
                af[mi][3] = __float_as_uint(Ab[(r0 + 8) * AS_STRIDE + kb + t + 4]);
            }
            #pragma unroll
            for (int ni = 0; ni < 4; ni++) {
                int c0 = wn * 32 + ni * 8 + g;
                bf[ni][0] = __float_as_uint(Bb[(kb + t    ) * BS_STRIDE + c0]);
                bf[ni][1] = __float_as_uint(Bb[(kb + t + 4) * BS_STRIDE + c0]);
            }
            #pragma unroll
            for (int mi = 0; mi < 4; mi++)
                #pragma unroll
                for (int ni = 0; ni < 4; ni++)
                    mma_tf32(acc[mi][ni], af[mi], bf[ni]);
        }
        // store prefetched tile into other buffer
        if (it + 1 < nIter) {
            float* Aw = As + (buf ^ 1) * AS_STAGE;
            float* Bw = Bs + (buf ^ 1) * BS_STAGE;
            #pragma unroll
            for (int i = 0; i < 4; i++) {
                float* a = &Aw[ar[i] * AS_STRIDE + ac[i]];
                a[0] = totf32(pa[i].x); a[1] = totf32(pa[i].y);
                a[2] = totf32(pa[i].z); a[3] = totf32(pa[i].w);
                float* bsp = &Bw[br[i] * BS_STRIDE + bc[i]];
                bsp[0] = totf32(pb[i].x); bsp[1] = totf32(pb[i].y);
                bsp[2] = totf32(pb[i].z); bsp[3] = totf32(pb[i].w);
            }
            __syncthreads();
        }
    }

    // epilogue
    #pragma unroll
    for (int mi = 0; mi < 4; mi++) {
        #pragma unroll
        for (int half = 0; half < 2; half++) {
            int row = bm + wm * 64 + mi * 16 + g + half * 8;
            #pragma unroll
            for (int ni = 0; ni < 4; ni++) {
                int col = bn + wn * 32 + ni * 8 + 2 * t;
                float v0 = acc[mi][ni][half * 2 + 0];
                float v1 = acc[mi][ni][half * 2 + 1];
                if (MODE == 1) {
                    float2 bb = *(const float2*)(bias + col);
                    v0 = geluf(v0 + bb.x); v1 = geluf(v1 + bb.y);
                } else if (MODE == 2) {
                    float2 bb = *(const float2*)(bias + col);
                    float2 rs = *(const float2*)(resid + (size_t)row * N + col);
                    v0 += bb.x + rs.x; v1 += bb.y + rs.y;
                } else if (MODE == 3) {
                    float2 rs = *(const float2*)(resid + (size_t)row * N + col);
                    v0 += rs.x; v1 += rs.y;
                }
                *(float2*)(C + (size_t)row * N + col) = make_float2(v0, v1);
            }
        }
    }
}

// ---------------- launch ----------------
extern "C" void kernel_launch(void* const* d_in, const int* in_sizes, int n_in,
                              void* d_out, int out_size)
{
    const float* x        = (const float*)d_in[0];
    const float* ln1_g    = (const float*)d_in[1];
    const float* ln1_b    = (const float*)d_in[2];
    const float* w_in     = (const float*)d_in[3];
    const float* conv_w   = (const float*)d_in[4];
    const float* x_proj_w = (const float*)d_in[5];
    const float* dt_w     = (const float*)d_in[6];
    const float* dt_b     = (const float*)d_in[7];
    const float* A_log    = (const float*)d_in[8];
    const float* Dp       = (const float*)d_in[9];
    const float* on_g     = (const float*)d_in[10];
    const float* on_b     = (const float*)d_in[11];
    const float* w_out    = (const float*)d_in[12];
    const float* ln2_g    = (const float*)d_in[13];
    const float* ln2_b    = (const float*)d_in[14];
    const float* fc1_w    = (const float*)d_in[15];
    const float* fc1_b    = (const float*)d_in[16];
    const float* fc2_w    = (const float*)d_in[17];
    const float* fc2_b    = (const float*)d_in[18];
    float* out = (float*)d_out;

    float *h1, *xz, *u, *xd, *dt, *y, *g, *x1, *h2, *hid;
    cudaGetSymbolAddress((void**)&h1,  g_h1);
    cudaGetSymbolAddress((void**)&xz,  g_xz);
    cudaGetSymbolAddress((void**)&u,   g_u);
    cudaGetSymbolAddress((void**)&xd,  g_xd);
    cudaGetSymbolAddress((void**)&dt,  g_dt);
    cudaGetSymbolAddress((void**)&y,   g_y);
    cudaGetSymbolAddress((void**)&g,   g_g);
    cudaGetSymbolAddress((void**)&x1,  g_x1);
    cudaGetSymbolAddress((void**)&h2,  g_h2);
    cudaGetSymbolAddress((void**)&hid, g_hid);

    // opt-in to >48KB dynamic smem (idempotent; host-side, not a stream op)
    cudaFuncSetAttribute(gemm_tc<0>, cudaFuncAttributeMaxDynamicSharedMemorySize, GEMM_SMEM);
    cudaFuncSetAttribute(gemm_tc<1>, cudaFuncAttributeMaxDynamicSharedMemorySize, GEMM_SMEM);
    cudaFuncSetAttribute(gemm_tc<2>, cudaFuncAttributeMaxDynamicSharedMemorySize, GEMM_SMEM);
    cudaFuncSetAttribute(gemm_tc<3>, cudaFuncAttributeMaxDynamicSharedMemorySize, GEMM_SMEM);
    cudaFuncSetAttribute(xdbl_kernel, cudaFuncAttributeMaxDynamicSharedMemorySize, 26 * DI * 4);

    // 1. h1 = LN(x)   (eps 1e-6)
    ln_kernel<<<NTOK / 8, 256>>>(x, ln1_g, ln1_b, h1, CDIM, 1e-6f);
    // 2. xz = h1 @ w_in
    gemm_tc<0><<<dim3(XZW / GBN, NTOK / GBM), 256, GEMM_SMEM>>>(h1, w_in, xz, NTOK, XZW, CDIM, nullptr, nullptr);
    // 3. u = silu(dwconv3x3(xm))
    conv_silu_kernel<<<NTOK, 256>>>(xz, conv_w, u);
    // 4. x_dbl = u @ x_proj_w
    xdbl_kernel<<<NTOK / 128, 256, 26 * DI * 4>>>(u, x_proj_w, xd);
    // 5. dt = softplus(dt_proj(xd) + b)
    dt_kernel<<<dim3(DI / 256, NTOK), 256>>>(xd, dt_w, dt_b, dt);
    // 6. selective scan + y
    scan_kernel<<<(NBAT * (DI / 32) * 32) / 256, 256>>>(u, dt, xd, A_log, Dp, y);
    // 7. g = LN_out(y) * silu(z)
    lngate_kernel<<<NTOK / 8, 256>>>(y, xz, on_g, on_b, g);
    // 8. x1 = g @ w_out + x
    gemm_tc<3><<<dim3(CDIM / GBN, NTOK / GBM), 256, GEMM_SMEM>>>(g, w_out, x1, NTOK, CDIM, DI, nullptr, x);
    // 9. h2 = LN(x1)
    ln_kernel<<<NTOK / 8, 256>>>(x1, ln2_g, ln2_b, h2, CDIM, 1e-6f);
    // 10. hid = gelu(h2 @ fc1_w + fc1_b)
    gemm_tc<1><<<dim3(HIDD / GBN, NTOK / GBM), 256, GEMM_SMEM>>>(h2, fc1_w, hid, NTOK, HIDD, CDIM, fc1_b, nullptr);
    // 11. out = hid @ fc2_w + fc2_b + x1
    gemm_tc<2><<<dim3(CDIM / GBN, NTOK / GBM), 256, GEMM_SMEM>>>(hid, fc2_w, out, NTOK, CDIM, HIDD, fc2_b, x1);
}

// round 4
// speedup vs baseline: 1.9974x; 1.0769x over previous
#include <cuda_runtime.h>
#include <math.h>
#include <stdint.h>

#define NTOK 16384
#define CDIM 384
#define DI   768
#define LLEN 1024
#define NBAT 16
#define HIDD 1536
#define XZW  1536   // 2*DI

// ---------------- scratch (device globals) ----------------
__device__ float g_h1 [NTOK * CDIM];
__device__ float g_xz [NTOK * XZW];
__device__ float g_u  [NTOK * DI];
__device__ float g_xd [NTOK * 26];
__device__ float g_dt [NTOK * DI];
__device__ float g_y  [NTOK * DI];
__device__ float g_g  [NTOK * DI];
__device__ float g_x1 [NTOK * CDIM];
__device__ float g_h2 [NTOK * CDIM];
__device__ float g_hid[NTOK * HIDD];
// tf32-rounded weights: w_in | w_out | fc1 | fc2
#define WR_WIN  0
#define WR_WOUT (CDIM * XZW)                    // 589824
#define WR_FC1  (WR_WOUT + DI * CDIM)           // 884736
#define WR_FC2  (WR_FC1 + CDIM * HIDD)          // 1474560
__device__ float g_wr [WR_FC2 + HIDD * CDIM];   // 2064384 floats

// ---------------- helpers ----------------
__device__ __forceinline__ float siluf(float x) { return x / (1.f + expf(-x)); }
__device__ __forceinline__ float geluf(float x) {
    float x3 = x * x * x;
    return 0.5f * x * (1.f + tanhf(0.7978845608028654f * (x + 0.044715f * x3)));
}
__device__ __forceinline__ float softplusf(float x) {
    return (x > 20.f) ? x : log1pf(expf(x));
}
__device__ __forceinline__ float totf32(float x) {
    uint32_t o;
    asm("cvt.rna.tf32.f32 %0, %1;" : "=r"(o) : "f"(x));
    return __uint_as_float(o);
}
__device__ __forceinline__ void mma_tf32(float* d, const uint32_t* a, const uint32_t* b) {
    asm volatile(
        "mma.sync.aligned.m16n8k8.row.col.f32.tf32.tf32.f32 "
        "{%0,%1,%2,%3}, {%4,%5,%6,%7}, {%8,%9}, {%0,%1,%2,%3};"
        : "+f"(d[0]), "+f"(d[1]), "+f"(d[2]), "+f"(d[3])
        : "r"(a[0]), "r"(a[1]), "r"(a[2]), "r"(a[3]), "r"(b[0]), "r"(b[1]));
}
__device__ __forceinline__ uint32_t smem_u32(const void* p) {
    return (uint32_t)__cvta_generic_to_shared(p);
}
__device__ __forceinline__ void cp_async16(uint32_t dst, const void* src) {
    asm volatile("cp.async.ca.shared.global [%0], [%1], 16;" :: "r"(dst), "l"(src));
}
__device__ __forceinline__ void cp_commit() {
    asm volatile("cp.async.commit_group;");
}
template <int N>
__device__ __forceinline__ void cp_wait() {
    asm volatile("cp.async.wait_group %0;" :: "n"(N));
}

// ---------------- weight tf32 rounding ----------------
__global__ void round_kernel(const float* __restrict__ s, float* __restrict__ d, int n)
{
    int i = blockIdx.x * 256 + threadIdx.x;
    if (i < n) d[i] = totf32(s[i]);
}

// ---------------- LayerNorm (warp per row) -> tf32-rounded output ----------------
__global__ void ln_kernel(const float* __restrict__ x, const float* __restrict__ gam,
                          const float* __restrict__ bet, float* __restrict__ out,
                          int ncols, float eps)
{
    int row  = blockIdx.x * (blockDim.x >> 5) + (threadIdx.x >> 5);
    int lane = threadIdx.x & 31;
    const float4* x4 = (const float4*)(x + (size_t)row * ncols);
    int cnt = (ncols >> 2) >> 5;
    float4 v[6];
    float s = 0.f, s2 = 0.f;
    for (int i = 0; i < cnt; i++) {
        v[i] = x4[lane + (i << 5)];
        s  += v[i].x + v[i].y + v[i].z + v[i].w;
        s2 += v[i].x * v[i].x + v[i].y * v[i].y + v[i].z * v[i].z + v[i].w * v[i].w;
    }
    #pragma unroll
    for (int o = 16; o; o >>= 1) {
        s  += __shfl_xor_sync(0xffffffffu, s,  o);
        s2 += __shfl_xor_sync(0xffffffffu, s2, o);
    }
    float inv_n = 1.f / (float)ncols;
    float mu = s * inv_n;
    float rstd = rsqrtf(fmaxf(s2 * inv_n - mu * mu, 0.f) + eps);
    float4* o4 = (float4*)(out + (size_t)row * ncols);
    const float4* g4 = (const float4*)gam;
    const float4* b4 = (const float4*)bet;
    for (int i = 0; i < cnt; i++) {
        float4 gg = g4[lane + (i << 5)], bb = b4[lane + (i << 5)];
        float4 r;
        r.x = totf32((v[i].x - mu) * rstd * gg.x + bb.x);
        r.y = totf32((v[i].y - mu) * rstd * gg.y + bb.y);
        r.z = totf32((v[i].z - mu) * rstd * gg.z + bb.z);
        r.w = totf32((v[i].w - mu) * rstd * gg.w + bb.w);
        o4[lane + (i << 5)] = r;
    }
}

// -------- depthwise 3x3 conv + silu: row-tiled, smem halo, 128-ch chunks --------
__global__ void conv_silu_kernel(const float* __restrict__ xz,
                                 const float* __restrict__ cw,
                                 float* __restrict__ u)
{
    __shared__ float sx[3][32][128];
    int cc = blockIdx.x << 7;      // channel chunk base (0..640)
    int h  = blockIdx.y;
    int b  = blockIdx.z;
    int tid = threadIdx.x;
    const float* base = xz + (size_t)(b << 10) * XZW;

    // load 3 rows x 32 w x 128 ch (zero-fill out-of-range rows)
    for (int i = tid; i < 3072; i += 256) {
        int idx = i << 2;
        int r = idx >> 12;
        int rem = idx & 4095;
        int w = rem >> 7, c = rem & 127;
        int hh = h + r - 1;
        float4 v = make_float4(0.f, 0.f, 0.f, 0.f);
        if ((unsigned)hh < 32u)
            v = *(const float4*)(base + (size_t)((hh << 5) + w) * XZW + cc + c);
        *(float4*)&sx[r][w][c] = v;
    }
    __syncthreads();

    int c  = tid & 127;
    int w0 = tid >> 7;     // 0 or 1
    float k[9];
    #pragma unroll
    for (int j = 0; j < 9; j++) k[j] = cw[(cc + c) * 9 + j];
    float* urow = u + (size_t)((b << 10) + (h << 5)) * DI + cc + c;
    #pragma unroll
    for (int i = 0; i < 16; i++) {
        int w = w0 + (i << 1);
        float acc = 0.f;
        #pragma unroll
        for (int kh = 0; kh < 3; kh++)
            #pragma unroll
            for (int kw = 0; kw < 3; kw++) {
                int ww = w + kw - 1;
                if ((unsigned)ww < 32u)
                    acc = fmaf(sx[kh][ww][c], k[kh * 3 + kw], acc);
            }
        urow[(size_t)w * DI] = siluf(acc);
    }
}

// ------------- x_dbl = u @ x_proj_w, W^T in smem, 32 tokens/block -------------
__global__ void xdbl_kernel(const float* __restrict__ u, const float* __restrict__ W,
                            float* __restrict__ xd)
{
    extern __shared__ float sW[];   // [26][768]
    int tid = threadIdx.x;
    for (int i = tid; i < 26 * DI; i += 256) {
        int k = i / DI, d = i - k * DI;
        sW[i] = W[(size_t)d * 26 + k];
    }
    __syncthreads();
    int warp = tid >> 5, lane = tid & 31;
    for (int rep = 0; rep < 4; rep++) {
        int tok = blockIdx.x * 32 + rep * 8 + warp;
        const float* ur = u + (size_t)tok * DI;
        float uc[24];
        #pragma unroll
        for (int i = 0; i < 24; i++) uc[i] = ur[lane + 32 * i];
        #pragma unroll 2
        for (int k = 0; k < 26; k++) {
            float s = 0.f;
            const float* wr = sW + k * DI;
            #pragma unroll
            for (int i = 0; i < 24; i++)
                s = fmaf(uc[i], wr[lane + 32 * i], s);
            #pragma unroll
            for (int o = 16; o; o >>= 1) s += __shfl_xor_sync(0xffffffffu, s, o);
            if (lane == 0) xd[(size_t)tok * 26 + k] = s;
        }
    }
}

// ------------- dt = softplus(xd[:, :24] @ dt_proj_w + b) -------------
__global__ void dt_kernel(const float* __restrict__ xd, const float* __restrict__ dtw,
                          const float* __restrict__ dtb, float* __restrict__ dto)
{
    int d   = blockIdx.x * 256 + threadIdx.x;
    int tok = blockIdx.y;
    const float* xr = xd + (size_t)tok * 26;
    float s = dtb[d];
    #pragma unroll
    for (int r = 0; r < 24; r++)
        s = fmaf(xr[r], dtw[(size_t)r * DI + d], s);
    dto[(size_t)tok * DI + d] = softplusf(s);
}

// --------- selective scan (DS=1) + y epilogue ---------
__global__ void scan_kernel(const float* __restrict__ u, const float* __restrict__ dt,
                            const float* __restrict__ xd,
                            const float* __restrict__ A_log, const float* __restrict__ Dp,
                            float* __restrict__ y)
{
    int gwarp = (blockIdx.x * blockDim.x + threadIdx.x) >> 5;
    int lane  = threadIdx.x & 31;
    int b = gwarp / (DI / 32);
    int d = (gwarp % (DI / 32)) * 32 + lane;

    float Aval = -expf(A_log[d]);
    float Dval = Dp[d];

    const float* up = u  + (size_t)b * LLEN * DI + d;
    const float* dp = dt + (size_t)b * LLEN * DI + d;
    const float* xp = xd + (size_t)b * LLEN * 26;
    float*       yp = y  + (size_t)b * LLEN * DI + d;

    float h = 0.f;
    float uv = up[0], dtv = dp[0], Bc = xp[24], Cc = xp[25];
    for (int l = 0; l < LLEN; l++) {
        float un = 0.f, dn = 0.f, Bn = 0.f, Cn = 0.f;
        if (l + 1 < LLEN) {
            un = up[(size_t)(l + 1) * DI];
            dn = dp[(size_t)(l + 1) * DI];
            Bn = xp[(l + 1) * 26 + 24];
            Cn = xp[(l + 1) * 26 + 25];
        }
        float dA = expf(dtv * Aval);
        h = fmaf(dA, h, dtv * Bc * uv);
        yp[(size_t)l * DI] = fmaf(h, Cc, uv * Dval);
        uv = un; dtv = dn; Bc = Bn; Cc = Cn;
    }
}

// ------------- out-norm over DI + gating, tf32-rounded output -------------
__global__ void lngate_kernel(const float* __restrict__ y, const float* __restrict__ xz,
                              const float* __restrict__ gam, const float* __restrict__ bet,
                              float* __restrict__ out)
{
    int t    = blockIdx.x * (blockDim.x >> 5) + (threadIdx.x >> 5);
    int lane = threadIdx.x & 31;
    const float4* y4 = (const float4*)(y + (size_t)t * DI);
    float4 v[6];
    float s = 0.f, s2 = 0.f;
    #pragma unroll
    for (int i = 0; i < 6; i++) {
        v[i] = y4[lane + (i << 5)];
        s  += v[i].x + v[i].y + v[i].z + v[i].w;
        s2 += v[i].x * v[i].x + v[i].y * v[i].y + v[i].z * v[i].z + v[i].w * v[i].w;
    }
    #pragma unroll
    for (int o = 16; o; o >>= 1) {
        s  += __shfl_xor_sync(0xffffffffu, s,  o);
        s2 += __shfl_xor_sync(0xffffffffu, s2, o);
    }
    float mu = s * (1.f / DI);
    float rstd = rsqrtf(fmaxf(s2 * (1.f / DI) - mu * mu, 0.f) + 1e-5f);
    const float4* z4 = (const float4*)(xz + (size_t)t * XZW + DI);
    const float4* g4 = (const float4*)gam;
    const float4* b4 = (const float4*)bet;
    float4* o4 = (float4*)(out + (size_t)t * DI);
    #pragma unroll
    for (int i = 0; i < 6; i++) {
        float4 zz = z4[lane + (i << 5)];
        float4 gg = g4[lane + (i << 5)], bb = b4[lane + (i << 5)];
        float4 r;
        r.x = totf32(((v[i].x - mu) * rstd * gg.x + bb.x) * siluf(zz.x));
        r.y = totf32(((v[i].y - mu) * rstd * gg.y + bb.y) * siluf(zz.y));
        r.z = totf32(((v[i].z - mu) * rstd * gg.z + bb.z) * siluf(zz.z));
        r.w = totf32(((v[i].w - mu) * rstd * gg.w + bb.w) * siluf(zz.w));
        o4[lane + (i << 5)] = r;
    }
}

// -------- TF32 TC GEMM, 4-stage cp.async pipeline. inputs pre-rounded to tf32 --------
// MODE: 0 plain, 1 bias+gelu(->tf32), 2 bias+resid, 3 resid
#define GBM 128
#define GBN 128
#define GBK 16
#define STAGES 4
#define ASTR 20        // GBK+4
#define BSTR 136       // GBN+8
#define ASTG (GBM * ASTR)   // 2560 floats
#define BSTG (GBK * BSTR)   // 2176 floats
#define GSMEM (STAGES * (ASTG + BSTG) * 4)   // 75776 bytes

template <int MODE>
__global__ void __launch_bounds__(256, 2)
gemm_tc(const float* __restrict__ A, const float* __restrict__ Bm,
        float* __restrict__ C, int M, int N, int K,
        const float* __restrict__ bias, const float* __restrict__ resid)
{
    extern __shared__ float sm[];
    float* As = sm;
    float* Bs = sm + STAGES * ASTG;

    int bm = blockIdx.y * GBM, bn = blockIdx.x * GBN;
    int tid = threadIdx.x;
    int warp = tid >> 5, lane = tid & 31;
    int wm = warp >> 2, wn = warp & 3;
    int g = lane >> 2, t = lane & 3;

    int arow[2], acol[2], brow[2], bcol[2];
    #pragma unroll
    for (int i = 0; i < 2; i++) {
        int f = tid + i * 256;
        arow[i] = f >> 2;  acol[i] = (f & 3) << 2;
        brow[i] = f >> 5;  bcol[i] = (f & 31) << 2;
    }

    auto load_stage = [&](int s, int k0) {
        float* Ad = As + s * ASTG;
        float* Bd = Bs + s * BSTG;
        #pragma unroll
        for (int i = 0; i < 2; i++) {
            cp_async16(smem_u32(&Ad[arow[i] * ASTR + acol[i]]),
                       A + (size_t)(bm + arow[i]) * K + k0 + acol[i]);
            cp_async16(smem_u32(&Bd[brow[i] * BSTR + bcol[i]]),
                       Bm + (size_t)(k0 + brow[i]) * N + bn + bcol[i]);
        }
        cp_commit();
    };

    int nIter = K / GBK;
    #pragma unroll
    for (int s = 0; s < STAGES - 1; s++) load_stage(s, s * GBK);

    float acc[4][4][4];
    #pragma unroll
    for (int i = 0; i < 4; i++)
        #pragma unroll
        for (int j = 0; j < 4; j++)
            #pragma unroll
            for (int r = 0; r < 4; r++) acc[i][j][r] = 0.f;

    for (int it = 0; it < nIter; it++) {
        cp_wait<STAGES - 2>();
        __syncthreads();
        int pf = it + STAGES - 1;
        if (pf < nIter) load_stage(pf % STAGES, pf * GBK);
        else            cp_commit();   // empty group keeps wait accounting exact

        const float* Ab = As + (it % STAGES) * ASTG;
        const float* Bb = Bs + (it % STAGES) * BSTG;
        #pragma unroll
        for (int ks = 0; ks < 2; ks++) {
            int kb = ks * 8;
            uint32_t af[4][4], bf[4][2];
            #pragma unroll
            for (int mi = 0; mi < 4; mi++) {
                int r0 = wm * 64 + mi * 16 + g;
                af[mi][0] = __float_as_uint(Ab[(r0    ) * ASTR + kb + t    ]);
                af[mi][1] = __float_as_uint(Ab[(r0 + 8) * ASTR + kb + t    ]);
                af[mi][2] = __float_as_uint(Ab[(r0    ) * ASTR + kb + t + 4]);
                af[mi][3] = __float_as_uint(Ab[(r0 + 8) * ASTR + kb + t + 4]);
            }
            #pragma unroll
            for (int ni = 0; ni < 4; ni++) {
                int c0 = wn * 32 + ni * 8 + g;
                bf[ni][0] = __float_as_uint(Bb[(kb + t    ) * BSTR + c0]);
                bf[ni][1] = __float_as_uint(Bb[(kb + t + 4) * BSTR + c0]);
            }
            #pragma unroll
            for (int mi = 0; mi < 4; mi++)
                #pragma unroll
                for (int ni = 0; ni < 4; ni++)
                    mma_tf32(acc[mi][ni], af[mi], bf[ni]);
        }
    }

    // epilogue
    #pragma unroll
    for (int mi = 0; mi < 4; mi++) {
        #pragma unroll
        for (int half = 0; half < 2; half++) {
            int row = bm + wm * 64 + mi * 16 + g + half * 8;
            #pragma unroll
            for (int ni = 0; ni < 4; ni++) {
                int col = bn + wn * 32 + ni * 8 + 2 * t;
                float v0 = acc[mi][ni][half * 2 + 0];
                float v1 = acc[mi][ni][half * 2 + 1];
                if (MODE == 1) {
                    float2 bb = *(const float2*)(bias + col);
                    v0 = totf32(geluf(v0 + bb.x));
                    v1 = totf32(geluf(v1 + bb.y));
                } else if (MODE == 2) {
                    float2 bb = *(const float2*)(bias + col);
                    float2 rs = *(const float2*)(resid + (size_t)row * N + col);
                    v0 += bb.x + rs.x; v1 += bb.y + rs.y;
                } else if (MODE == 3) {
                    float2 rs = *(const float2*)(resid + (size_t)row * N + col);
                    v0 += rs.x; v1 += rs.y;
                }
                *(float2*)(C + (size_t)row * N + col) = make_float2(v0, v1);
            }
        }
    }
}

// ---------------- launch ----------------
extern "C" void kernel_launch(void* const* d_in, const int* in_sizes, int n_in,
                              void* d_out, int out_size)
{
    const float* x        = (const float*)d_in[0];
    const float* ln1_g    = (const float*)d_in[1];
    const float* ln1_b    = (const float*)d_in[2];
    const float* w_in     = (const float*)d_in[3];
    const float* conv_w   = (const float*)d_in[4];
    const float* x_proj_w = (const float*)d_in[5];
    const float* dt_w     = (const float*)d_in[6];
    const float* dt_b     = (const float*)d_in[7];
    const float* A_log    = (const float*)d_in[8];
    const float* Dp       = (const float*)d_in[9];
    const float* on_g     = (const float*)d_in[10];
    const float* on_b     = (const float*)d_in[11];
    const float* w_out    = (const float*)d_in[12];
    const float* ln2_g    = (const float*)d_in[13];
    const float* ln2_b    = (const float*)d_in[14];
    const float* fc1_w    = (const float*)d_in[15];
    const float* fc1_b    = (const float*)d_in[16];
    const float* fc2_w    = (const float*)d_in[17];
    const float* fc2_b    = (const float*)d_in[18];
    float* out = (float*)d_out;

    float *h1, *xz, *u, *xd, *dt, *y, *g, *x1, *h2, *hid, *wr;
    cudaGetSymbolAddress((void**)&h1,  g_h1);
    cudaGetSymbolAddress((void**)&xz,  g_xz);
    cudaGetSymbolAddress((void**)&u,   g_u);
    cudaGetSymbolAddress((void**)&xd,  g_xd);
    cudaGetSymbolAddress((void**)&dt,  g_dt);
    cudaGetSymbolAddress((void**)&y,   g_y);
    cudaGetSymbolAddress((void**)&g,   g_g);
    cudaGetSymbolAddress((void**)&x1,  g_x1);
    cudaGetSymbolAddress((void**)&h2,  g_h2);
    cudaGetSymbolAddress((void**)&hid, g_hid);
    cudaGetSymbolAddress((void**)&wr,  g_wr);

    cudaFuncSetAttribute(gemm_tc<0>, cudaFuncAttributeMaxDynamicSharedMemorySize, GSMEM);
    cudaFuncSetAttribute(gemm_tc<1>, cudaFuncAttributeMaxDynamicSharedMemorySize, GSMEM);
    cudaFuncSetAttribute(gemm_tc<2>, cudaFuncAttributeMaxDynamicSharedMemorySize, GSMEM);
    cudaFuncSetAttribute(gemm_tc<3>, cudaFuncAttributeMaxDynamicSharedMemorySize, GSMEM);
    cudaFuncSetAttribute(xdbl_kernel, cudaFuncAttributeMaxDynamicSharedMemorySize, 26 * DI * 4);

    // 0. round weights to tf32 once per call
    round_kernel<<<(CDIM * XZW + 255) / 256, 256>>>(w_in,  wr + WR_WIN,  CDIM * XZW);
    round_kernel<<<(DI * CDIM + 255) / 256, 256>>>(w_out, wr + WR_WOUT, DI * CDIM);
    round_kernel<<<(CDIM * HIDD + 255) / 256, 256>>>(fc1_w, wr + WR_FC1, CDIM * HIDD);
    round_kernel<<<(HIDD * CDIM + 255) / 256, 256>>>(fc2_w, wr + WR_FC2, HIDD * CDIM);

    // 1. h1 = LN(x), tf32-rounded
    ln_kernel<<<NTOK / 8, 256>>>(x, ln1_g, ln1_b, h1, CDIM, 1e-6f);
    // 2. xz = h1 @ w_in
    gemm_tc<0><<<dim3(XZW / GBN, NTOK / GBM), 256, GSMEM>>>(h1, wr + WR_WIN, xz, NTOK, XZW, CDIM, nullptr, nullptr);
    // 3. u = silu(dwconv3x3(xm))
    conv_silu_kernel<<<dim3(DI / 128, 32, NBAT), 256>>>(xz, conv_w, u);
    // 4. x_dbl = u @ x_proj_w
    xdbl_kernel<<<NTOK / 32, 256, 26 * DI * 4>>>(u, x_proj_w, xd);
    // 5. dt
    dt_kernel<<<dim3(DI / 256, NTOK), 256>>>(xd, dt_w, dt_b, dt);
    // 6. scan
    scan_kernel<<<(NBAT * (DI / 32) * 32) / 256, 256>>>(u, dt, xd, A_log, Dp, y);
    // 7. g = LN_out(y) * silu(z), tf32-rounded
    lngate_kernel<<<NTOK / 8, 256>>>(y, xz, on_g, on_b, g);
    // 8. x1 = g @ w_out + x
    gemm_tc<3><<<dim3(CDIM / GBN, NTOK / GBM), 256, GSMEM>>>(g, wr + WR_WOUT, x1, NTOK, CDIM, DI, nullptr, x);
    // 9. h2 = LN(x1), tf32-rounded
    ln_kernel<<<NTOK / 8, 256>>>(x1, ln2_g, ln2_b, h2, CDIM, 1e-6f);
    // 10. hid = gelu(h2 @ fc1_w + fc1_b), tf32-rounded
    gemm_tc<1><<<dim3(HIDD / GBN, NTOK / GBM), 256, GSMEM>>>(h2, wr + WR_FC1, hid, NTOK, HIDD, CDIM, fc1_b, nullptr);
    // 11. out = hid @ fc2_w + fc2_b + x1
    gemm_tc<2><<<dim3(CDIM / GBN, NTOK / GBM), 256, GSMEM>>>(hid, wr + WR_FC2, out, NTOK, CDIM, HIDD, fc2_b, x1);
}

// round 9
// speedup vs baseline: 2.4218x; 1.2125x over previous
#include <cuda_runtime.h>
#include <cuda_fp16.h>
#include <math.h>
#include <stdint.h>

#define NTOK 16384
#define CDIM 384
#define DI   768
#define LLEN 1024
#define NBAT 16
#define HIDD 1536
#define XZW  1536   // 2*DI

// ---------------- scratch (device globals) ----------------
__device__ __half g_h1 [NTOK * CDIM];
__device__ float  g_xz [NTOK * XZW];
__device__ float  g_u  [NTOK * DI];
__device__ float  g_xd [NTOK * 26];
__device__ float  g_dt [NTOK * DI];
__device__ float  g_y  [NTOK * DI];
__device__ __half g_g  [NTOK * DI];
__device__ float  g_x1 [NTOK * CDIM];
__device__ __half g_h2 [NTOK * CDIM];
__device__ __half g_hid[NTOK * HIDD];
// fp16, TRANSPOSED weights ([N][K] K-major): w_in | w_out | fc1 | fc2
#define WR_WIN  0
#define WR_WOUT (CDIM * XZW)
#define WR_FC1  (WR_WOUT + DI * CDIM)
#define WR_FC2  (WR_FC1 + CDIM * HIDD)
__device__ __half g_wr [WR_FC2 + HIDD * CDIM];

// ---------------- helpers ----------------
__device__ __forceinline__ float siluf(float x) { return x / (1.f + expf(-x)); }
__device__ __forceinline__ float geluf(float x) {
    float x3 = x * x * x;
    return 0.5f * x * (1.f + tanhf(0.7978845608028654f * (x + 0.044715f * x3)));
}
__device__ __forceinline__ float softplusf(float x) {
    return (x > 20.f) ? x : log1pf(expf(x));
}
__device__ __forceinline__ uint32_t smem_u32(const void* p) {
    return (uint32_t)__cvta_generic_to_shared(p);
}
__device__ __forceinline__ void cp_async16(uint32_t dst, const void* src) {
    asm volatile("cp.async.ca.shared.global [%0], [%1], 16;" :: "r"(dst), "l"(src));
}
__device__ __forceinline__ void cp_commit() { asm volatile("cp.async.commit_group;"); }
template <int N>
__device__ __forceinline__ void cp_wait() {
    asm volatile("cp.async.wait_group %0;" :: "n"(N));
}
// fp16 mma m16n8k16, f32 accumulate
__device__ __forceinline__ void mma_f16(float* d, const uint32_t* a, const uint32_t* b) {
    asm volatile(
        "mma.sync.aligned.m16n8k16.row.col.f32.f16.f16.f32 "
        "{%0,%1,%2,%3}, {%4,%5,%6,%7}, {%8,%9}, {%0,%1,%2,%3};"
        : "+f"(d[0]), "+f"(d[1]), "+f"(d[2]), "+f"(d[3])
        : "r"(a[0]), "r"(a[1]), "r"(a[2]), "r"(a[3]), "r"(b[0]), "r"(b[1]));
}

// -------- weight transpose + fp16: dst[N][K] = half(src[K][N]) --------
__global__ void tpose_kernel(const float* __restrict__ src, __half* __restrict__ dst,
                             int K, int N)
{
    __shared__ float t[32][33];
    int kb = blockIdx.x << 5, nb = blockIdx.y << 5;
    int tx = threadIdx.x & 31, ty = threadIdx.x >> 5;
    #pragma unroll
    for (int i = 0; i < 32; i += 8)
        t[ty + i][tx] = src[(size_t)(kb + ty + i) * N + nb + tx];
    __syncthreads();
    #pragma unroll
    for (int i = 0; i < 32; i += 8)
        dst[(size_t)(nb + ty + i) * K + kb + tx] = __float2half(t[tx][ty + i]);
}

// ---------------- LayerNorm (warp per row) -> fp16 output ----------------
__global__ void ln_kernel(const float* __restrict__ x, const float* __restrict__ gam,
                          const float* __restrict__ bet, __half* __restrict__ out,
                          int ncols, float eps)
{
    int row  = blockIdx.x * (blockDim.x >> 5) + (threadIdx.x >> 5);
    int lane = threadIdx.x & 31;
    const float4* x4 = (const float4*)(x + (size_t)row * ncols);
    int cnt = (ncols >> 2) >> 5;
    float4 v[6];
    float s = 0.f, s2 = 0.f;
    for (int i = 0; i < cnt; i++) {
        v[i] = x4[lane + (i << 5)];
        s  += v[i].x + v[i].y + v[i].z + v[i].w;
        s2 += v[i].x * v[i].x + v[i].y * v[i].y + v[i].z * v[i].z + v[i].w * v[i].w;
    }
    #pragma unroll
    for (int o = 16; o; o >>= 1) {
        s  += __shfl_xor_sync(0xffffffffu, s,  o);
        s2 += __shfl_xor_sync(0xffffffffu, s2, o);
    }
    float inv_n = 1.f / (float)ncols;
    float mu = s * inv_n;
    float rstd = rsqrtf(fmaxf(s2 * inv_n - mu * mu, 0.f) + eps);
    const float4* g4 = (const float4*)gam;
    const float4* b4 = (const float4*)bet;
    __half2* o2 = (__half2*)(out + (size_t)row * ncols);
    for (int i = 0; i < cnt; i++) {
        float4 gg = g4[lane + (i << 5)], bb = b4[lane + (i << 5)];
        float rx = (v[i].x - mu) * rstd * gg.x + bb.x;
        float ry = (v[i].y - mu) * rstd * gg.y + bb.y;
        float rz = (v[i].z - mu) * rstd * gg.z + bb.z;
        float rw = (v[i].w - mu) * rstd * gg.w + bb.w;
        o2[2 * (lane + (i << 5))]     = __floats2half2_rn(rx, ry);
        o2[2 * (lane + (i << 5)) + 1] = __floats2half2_rn(rz, rw);
    }
}

// -------- depthwise 3x3 conv + silu: row-tiled, smem halo, 128-ch chunks --------
__global__ void conv_silu_kernel(const float* __restrict__ xz,
                                 const float* __restrict__ cw,
                                 float* __restrict__ u)
{
    __shared__ float sx[3][32][128];
    int cc = blockIdx.x << 7;
    int h  = blockIdx.y;
    int b  = blockIdx.z;
    int tid = threadIdx.x;
    const float* base = xz + (size_t)(b << 10) * XZW;

    for (int i = tid; i < 3072; i += 256) {
        int idx = i << 2;
        int r = idx >> 12;
        int rem = idx & 4095;
        int w = rem >> 7, c = rem & 127;
        int hh = h + r - 1;
        float4 v = make_float4(0.f, 0.f, 0.f, 0.f);
        if ((unsigned)hh < 32u)
            v = *(const float4*)(base + (size_t)((hh << 5) + w) * XZW + cc + c);
        *(float4*)&sx[r][w][c] = v;
    }
    __syncthreads();

    int c  = tid & 127;
    int w0 = tid >> 7;
    float k[9];
    #pragma unroll
    for (int j = 0; j < 9; j++) k[j] = cw[(cc + c) * 9 + j];
    float* urow = u + (size_t)((b << 10) + (h << 5)) * DI + cc + c;
    #pragma unroll
    for (int i = 0; i < 16; i++) {
        int w = w0 + (i << 1);
        float acc = 0.f;
        #pragma unroll
        for (int kh = 0; kh < 3; kh++)
            #pragma unroll
            for (int kw = 0; kw < 3; kw++) {
                int ww = w + kw - 1;
                if ((unsigned)ww < 32u)
                    acc = fmaf(sx[kh][ww][c], k[kh * 3 + kw], acc);
            }
        urow[(size_t)w * DI] = siluf(acc);
    }
}

// ------------- x_dbl = u @ x_proj_w, W^T in smem, 32 tokens/block -------------
__global__ void xdbl_kernel(const float* __restrict__ u, const float* __restrict__ W,
                            float* __restrict__ xd)
{
    extern __shared__ float sW[];
    int tid = threadIdx.x;
    for (int i = tid; i < 26 * DI; i += 256) {
        int k = i / DI, d = i - k * DI;
        sW[i] = W[(size_t)d * 26 + k];
    }
    __syncthreads();
    int warp = tid >> 5, lane = tid & 31;
    for (int rep = 0; rep < 4; rep++) {
        int tok = blockIdx.x * 32 + rep * 8 + warp;
        const float* ur = u + (size_t)tok * DI;
        float uc[24];
        #pragma unroll
        for (int i = 0; i < 24; i++) uc[i] = ur[lane + 32 * i];
        #pragma unroll 2
        for (int k = 0; k < 26; k++) {
            float s = 0.f;
            const float* wr = sW + k * DI;
            #pragma unroll
            for (int i = 0; i < 24; i++)
                s = fmaf(uc[i], wr[lane + 32 * i], s);
            #pragma unroll
            for (int o = 16; o; o >>= 1) s += __shfl_xor_sync(0xffffffffu, s, o);
            if (lane == 0) xd[(size_t)tok * 26 + k] = s;
        }
    }
}

// ------------- dt = softplus(xd[:, :24] @ dt_proj_w + b) -------------
__global__ void dt_kernel(const float* __restrict__ xd, const float* __restrict__ dtw,
                          const float* __restrict__ dtb, float* __restrict__ dto)
{
    int d   = blockIdx.x * 256 + threadIdx.x;
    int tok = blockIdx.y;
    const float* xr = xd + (size_t)tok * 26;
    float s = dtb[d];
    #pragma unroll
    for (int r = 0; r < 24; r++)
        s = fmaf(xr[r], dtw[(size_t)r * DI + d], s);
    dto[(size_t)tok * DI + d] = softplusf(s);
}

// --------- selective scan (DS=1) + y epilogue ---------
__global__ void scan_kernel(const float* __restrict__ u, const float* __restrict__ dt,
                            const float* __restrict__ xd,
                            const float* __restrict__ A_log, const float* __restrict__ Dp,
                            float* __restrict__ y)
{
    int gwarp = (blockIdx.x * blockDim.x + threadIdx.x) >> 5;
    int lane  = threadIdx.x & 31;
    int b = gwarp / (DI / 32);
    int d = (gwarp % (DI / 32)) * 32 + lane;

    float Aval = -expf(A_log[d]);
    float Dval = Dp[d];

    const float* up = u  + (size_t)b * LLEN * DI + d;
    const float* dp = dt + (size_t)b * LLEN * DI + d;
    const float* xp = xd + (size_t)b * LLEN * 26;
    float*       yp = y  + (size_t)b * LLEN * DI + d;

    float h = 0.f;
    float uv = up[0], dtv = dp[0], Bc = xp[24], Cc = xp[25];
    for (int l = 0; l < LLEN; l++) {
        float un = 0.f, dn = 0.f, Bn = 0.f, Cn = 0.f;
        if (l + 1 < LLEN) {
            un = up[(size_t)(l + 1) * DI];
            dn = dp[(size_t)(l + 1) * DI];
            Bn = xp[(l + 1) * 26 + 24];
            Cn = xp[(l + 1) * 26 + 25];
        }
        float dA = expf(dtv * Aval);
        h = fmaf(dA, h, dtv * Bc * uv);
        yp[(size_t)l * DI] = fmaf(h, Cc, uv * Dval);
        uv = un; dtv = dn; Bc = Bn; Cc = Cn;
    }
}

// ------------- out-norm over DI + gating -> fp16 output -------------
__global__ void lngate_kernel(const float* __restrict__ y, const float* __restrict__ xz,
                              const float* __restrict__ gam, const float* __restrict__ bet,
                              __half* __restrict__ out)
{
    int t    = blockIdx.x * (blockDim.x >> 5) + (threadIdx.x >> 5);
    int lane = threadIdx.x & 31;
    const float4* y4 = (const float4*)(y + (size_t)t * DI);
    float4 v[6];
    float s = 0.f, s2 = 0.f;
    #pragma unroll
    for (int i = 0; i < 6; i++) {
        v[i] = y4[lane + (i << 5)];
        s  += v[i].x + v[i].y + v[i].z + v[i].w;
        s2 += v[i].x * v[i].x + v[i].y * v[i].y + v[i].z * v[i].z + v[i].w * v[i].w;
    }
    #pragma unroll
    for (int o = 16; o; o >>= 1) {
        s  += __shfl_xor_sync(0xffffffffu, s,  o);
        s2 += __shfl_xor_sync(0xffffffffu, s2, o);
    }
    float mu = s * (1.f / DI);
    float rstd = rsqrtf(fmaxf(s2 * (1.f / DI) - mu * mu, 0.f) + 1e-5f);
    const float4* z4 = (const float4*)(xz + (size_t)t * XZW + DI);
    const float4* g4 = (const float4*)gam;
    const float4* b4 = (const float4*)bet;
    __half2* o2 = (__half2*)(out + (size_t)t * DI);
    #pragma unroll
    for (int i = 0; i < 6; i++) {
        float4 zz = z4[lane + (i << 5)];
        float4 gg = g4[lane + (i << 5)], bb = b4[lane + (i << 5)];
        float rx = ((v[i].x - mu) * rstd * gg.x + bb.x) * siluf(zz.x);
        float ry = ((v[i].y - mu) * rstd * gg.y + bb.y) * siluf(zz.y);
        float rz = ((v[i].z - mu) * rstd * gg.z + bb.z) * siluf(zz.z);
        float rw = ((v[i].w - mu) * rstd * gg.w + bb.w) * siluf(zz.w);
        o2[2 * (lane + (i << 5))]     = __floats2half2_rn(rx, ry);
        o2[2 * (lane + (i << 5)) + 1] = __floats2half2_rn(rz, rw);
    }
}

// ===== fp16 TC GEMM: C[M,N] = A[M,K](half) @ Bt[N,K](half)^T, f32 accum =====
// MODE: 0 plain->f32, 1 bias+gelu->f16, 2 bias+resid->f32, 3 resid->f32
#define GBM 128
#define GBN 128
#define GBK 32
#define STAGES 4
#define HSTR 40                      // halves per smem row (32 + 8 pad)
#define ASTG (GBM * HSTR)            // 5120 halves
#define BSTG (GBN * HSTR)
#define GSMEM (STAGES * (ASTG + BSTG) * 2)   // 81920 bytes

template <int MODE, typename OutT>
__global__ void __launch_bounds__(256, 2)
gemm_f16(const __half* __restrict__ A, const __half* __restrict__ Bt,
         OutT* __restrict__ C, int M, int N, int K,
         const float* __restrict__ bias, const float* __restrict__ resid)
{
    extern __shared__ __half sh[];
    __half* As = sh;
    __half* Bs = sh + STAGES * ASTG;

    int bm = blockIdx.y * GBM, bn = blockIdx.x * GBN;
    int tid = threadIdx.x;
    int warp = tid >> 5, lane = tid & 31;
    int wm = warp >> 2, wn = warp & 3;      // 2x4 warps: 64x32 per warp
    int g = lane >> 2, t = lane & 3;

    // loader geometry: 512 16B-chunks each for A and B per stage; 2 each per thread
    int rowi[2], chk[2];
    #pragma unroll
    for (int i = 0; i < 2; i++) {
        int f = tid + i * 256;
        rowi[i] = f >> 2;
        chk[i]  = (f & 3) << 3;   // halves offset within row
    }

    auto load_stage = [&](int s, int k0) {
        __half* Ad = As + s * ASTG;
        __half* Bd = Bs + s * BSTG;
        #pragma unroll
        for (int i = 0; i < 2; i++) {
            cp_async16(smem_u32(&Ad[rowi[i] * HSTR + chk[i]]),
                       A + (size_t)(bm + rowi[i]) * K + k0 + chk[i]);
            cp_async16(smem_u32(&Bd[rowi[i] * HSTR + chk[i]]),
                       Bt + (size_t)(bn + rowi[i]) * K + k0 + chk[i]);
        }
        cp_commit();
    };

    int nIter = K / GBK;
    #pragma unroll
    for (int s = 0; s < STAGES - 1; s++) load_stage(s, s * GBK);

    float acc[4][4][4];
    #pragma unroll
    for (int i = 0; i < 4; i++)
        #pragma unroll
        for (int j = 0; j < 4; j++)
            #pragma unroll
            for (int r = 0; r < 4; r++) acc[i][j][r] = 0.f;

    for (int it = 0; it < nIter; it++) {
        cp_wait<STAGES - 2>();
        __syncthreads();
        int pf = it + STAGES - 1;
        if (pf < nIter) load_stage(pf % STAGES, pf * GBK);
        else            cp_commit();   // keep wait-group accounting exact

        const __half* Ab = As + (it % STAGES) * ASTG;
        const __half* Bb = Bs + (it % STAGES) * BSTG;
        #pragma unroll
        for (int ks = 0; ks < 2; ks++) {
            int kb = ks * 16;
            uint32_t af[4][4], bf[4][2];
            #pragma unroll
            for (int mi = 0; mi < 4; mi++) {
                int r0 = wm * 64 + mi * 16 + g;
                af[mi][0] = *(const uint32_t*)&Ab[(r0    ) * HSTR + kb + 2 * t    ];
                af[mi][1] = *(const uint32_t*)&Ab[(r0 + 8) * HSTR + kb + 2 * t    ];
                af[mi][2] = *(const uint32_t*)&Ab[(r0    ) * HSTR + kb + 2 * t + 8];
                af[mi][3] = *(const uint32_t*)&Ab[(r0 + 8) * HSTR + kb + 2 * t + 8];
            }
            #pragma unroll
            for (int ni = 0; ni < 4; ni++) {
                int c0 = wn * 32 + ni * 8 + g;
                bf[ni][0] = *(const uint32_t*)&Bb[c0 * HSTR + kb + 2 * t    ];
                bf[ni][1] = *(const uint32_t*)&Bb[c0 * HSTR + kb + 2 * t + 8];
            }
            #pragma unroll
            for (int mi = 0; mi < 4; mi++)
                #pragma unroll
                for (int ni = 0; ni < 4; ni++)
                    mma_f16(acc[mi][ni], af[mi], bf[ni]);
        }
    }

    // epilogue
    #pragma unroll
    for (int mi = 0; mi < 4; mi++) {
        #pragma unroll
        for (int half_ = 0; half_ < 2; half_++) {
            int row = bm + wm * 64 + mi * 16 + g + half_ * 8;
            #pragma unroll
            for (int ni = 0; ni < 4; ni++) {
                int col = bn + wn * 32 + ni * 8 + 2 * t;
                float v0 = acc[mi][ni][half_ * 2 + 0];
                float v1 = acc[mi][ni][half_ * 2 + 1];
                if (MODE == 1) {
                    float2 bb = *(const float2*)(bias + col);
                    __half2 hv = __floats2half2_rn(geluf(v0 + bb.x), geluf(v1 + bb.y));
                    *(__half2*)((__half*)C + (size_t)row * N + col) = hv;
                } else {
                    if (MODE == 2) {
                        float2 bb = *(const float2*)(bias + col);
                        float2 rs = *(const float2*)(resid + (size_t)row * N + col);
                        v0 += bb.x + rs.x; v1 += bb.y + rs.y;
                    } else if (MODE == 3) {
                        float2 rs = *(const float2*)(resid + (size_t)row * N + col);
                        v0 += rs.x; v1 += rs.y;
                    }
                    *(float2*)((float*)C + (size_t)row * N + col) = make_float2(v0, v1);
                }
            }
        }
    }
}

// ---------------- launch ----------------
extern "C" void kernel_launch(void* const* d_in, const int* in_sizes, int n_in,
                              void* d_out, int out_size)
{
    const float* x        = (const float*)d_in[0];
    const float* ln1_g    = (const float*)d_in[1];
    const float* ln1_b    = (const float*)d_in[2];
    const float* w_in     = (const float*)d_in[3];
    const float* conv_w   = (const float*)d_in[4];
    const float* x_proj_w = (const float*)d_in[5];
    const float* dt_w     = (const float*)d_in[6];
    const float* dt_b     = (const float*)d_in[7];
    const float* A_log    = (const float*)d_in[8];
    const float* Dp       = (const float*)d_in[9];
    const float* on_g     = (const float*)d_in[10];
    const float* on_b     = (const float*)d_in[11];
    const float* w_out    = (const float*)d_in[12];
    const float* ln2_g    = (const float*)d_in[13];
    const float* ln2_b    = (const float*)d_in[14];
    const float* fc1_w    = (const float*)d_in[15];
    const float* fc1_b    = (const float*)d_in[16];
    const float* fc2_w    = (const float*)d_in[17];
    const float* fc2_b    = (const float*)d_in[18];
    float* out = (float*)d_out;

    __half *h1, *g, *h2, *hid, *wr;
    float *xz, *u, *xd, *dt, *y, *x1;
    cudaGetSymbolAddress((void**)&h1,  g_h1);
    cudaGetSymbolAddress((void**)&xz,  g_xz);
    cudaGetSymbolAddress((void**)&u,   g_u);
    cudaGetSymbolAddress((void**)&xd,  g_xd);
    cudaGetSymbolAddress((void**)&dt,  g_dt);
    cudaGetSymbolAddress((void**)&y,   g_y);
    cudaGetSymbolAddress((void**)&g,   g_g);
    cudaGetSymbolAddress((void**)&x1,  g_x1);
    cudaGetSymbolAddress((void**)&h2,  g_h2);
    cudaGetSymbolAddress((void**)&hid, g_hid);
    cudaGetSymbolAddress((void**)&wr,  g_wr);

    cudaFuncSetAttribute(gemm_f16<0, float >, cudaFuncAttributeMaxDynamicSharedMemorySize, GSMEM);
    cudaFuncSetAttribute(gemm_f16<1, __half>, cudaFuncAttributeMaxDynamicSharedMemorySize, GSMEM);
    cudaFuncSetAttribute(gemm_f16<2, float >, cudaFuncAttributeMaxDynamicSharedMemorySize, GSMEM);
    cudaFuncSetAttribute(gemm_f16<3, float >, cudaFuncAttributeMaxDynamicSharedMemorySize, GSMEM);
    cudaFuncSetAttribute(xdbl_kernel, cudaFuncAttributeMaxDynamicSharedMemorySize, 26 * DI * 4);

    // 0. transpose + fp16 weights: [K,N] -> [N,K]
    tpose_kernel<<<dim3(CDIM / 32, XZW / 32), 256>>>(w_in,  wr + WR_WIN,  CDIM, XZW);
    tpose_kernel<<<dim3(DI / 32, CDIM / 32), 256>>>(w_out, wr + WR_WOUT, DI, CDIM);
    tpose_kernel<<<dim3(CDIM / 32, HIDD / 32), 256>>>(fc1_w, wr + WR_FC1, CDIM, HIDD);
    tpose_kernel<<<dim3(HIDD / 32, CDIM / 32), 256>>>(fc2_w, wr + WR_FC2, HIDD, CDIM);

    // 1. h1 = LN(x) -> fp16
    ln_kernel<<<NTOK / 8, 256>>>(x, ln1_g, ln1_b, h1, CDIM, 1e-6f);
    // 2. xz = h1 @ w_in  (f32 out)
    gemm_f16<0, float><<<dim3(XZW / GBN, NTOK / GBM), 256, GSMEM>>>(
        h1, wr + WR_WIN, xz, NTOK, XZW, CDIM, nullptr, nullptr);
    // 3. u = silu(dwconv3x3(xm))
    conv_silu_kernel<<<dim3(DI / 128, 32, NBAT), 256>>>(xz, conv_w, u);
    // 4. x_dbl = u @ x_proj_w
    xdbl_kernel<<<NTOK / 32, 256, 26 * DI * 4>>>(u, x_proj_w, xd);
    // 5. dt
    dt_kernel<<<dim3(DI / 256, NTOK), 256>>>(xd, dt_w, dt_b, dt);
    // 6. scan
    scan_kernel<<<(NBAT * (DI / 32) * 32) / 256, 256>>>(u, dt, xd, A_log, Dp, y);
    // 7. g = LN_out(y) * silu(z) -> fp16
    lngate_kernel<<<NTOK / 8, 256>>>(y, xz, on_g, on_b, g);
    // 8. x1 = g @ w_out + x  (f32 out)
    gemm_f16<3, float><<<dim3(CDIM / GBN, NTOK / GBM), 256, GSMEM>>>(
        g, wr + WR_WOUT, x1, NTOK, CDIM, DI, nullptr, x);
    // 9. h2 = LN(x1) -> fp16
    ln_kernel<<<NTOK / 8, 256>>>(x1, ln2_g, ln2_b, h2, CDIM, 1e-6f);
    // 10. hid = gelu(h2 @ fc1_w + fc1_b) -> fp16
    gemm_f16<1, __half><<<dim3(HIDD / GBN, NTOK / GBM), 256, GSMEM>>>(
        h2, wr + WR_FC1, hid, NTOK, HIDD, CDIM, fc1_b, nullptr);
    // 11. out = hid @ fc2_w + fc2_b + x1  (f32 out)
    gemm_f16<2, float><<<dim3(CDIM / GBN, NTOK / GBM), 256, GSMEM>>>(
        hid, wr + WR_FC2, out, NTOK, CDIM, HIDD, fc2_b, x1);
}

// round 12
// speedup vs baseline: 2.8691x; 1.1847x over previous
#include <cuda_runtime.h>
#include <cuda_fp16.h>
#include <math.h>
#include <stdint.h>

#define NTOK 16384
#define CDIM 384
#define DI   768
#define LLEN 1024
#define NBAT 16
#define HIDD 1536
#define XZW  1536   // 2*DI

// ---------------- scratch (device globals) ----------------
__device__ __half g_h1 [NTOK * CDIM];
__device__ __half g_xz [NTOK * XZW];
__device__ __half g_u  [NTOK * DI];
__device__ float  g_xd [NTOK * 26];
__device__ __half g_dt [NTOK * DI];
__device__ __half g_y  [NTOK * DI];
__device__ __half g_g  [NTOK * DI];
__device__ float  g_x1 [NTOK * CDIM];
__device__ __half g_h2 [NTOK * CDIM];
__device__ __half g_hid[NTOK * HIDD];
// fp16, TRANSPOSED weights ([N][K] K-major): w_in | w_out | fc1 | fc2
#define WR_WIN  0
#define WR_WOUT (CDIM * XZW)
#define WR_FC1  (WR_WOUT + DI * CDIM)
#define WR_FC2  (WR_FC1 + CDIM * HIDD)
__device__ __half g_wr [WR_FC2 + HIDD * CDIM];

// ---------------- helpers ----------------
__device__ __forceinline__ float siluf(float x) { return x / (1.f + expf(-x)); }
__device__ __forceinline__ float geluf(float x) {
    float x3 = x * x * x;
    return 0.5f * x * (1.f + tanhf(0.7978845608028654f * (x + 0.044715f * x3)));
}
__device__ __forceinline__ float softplusf(float x) {
    return (x > 20.f) ? x : log1pf(expf(x));
}
__device__ __forceinline__ uint32_t smem_u32(const void* p) {
    return (uint32_t)__cvta_generic_to_shared(p);
}
__device__ __forceinline__ void cp_async16(uint32_t dst, const void* src) {
    asm volatile("cp.async.ca.shared.global [%0], [%1], 16;" :: "r"(dst), "l"(src));
}
__device__ __forceinline__ void cp_commit() { asm volatile("cp.async.commit_group;"); }
template <int N>
__device__ __forceinline__ void cp_wait() {
    asm volatile("cp.async.wait_group %0;" :: "n"(N));
}
__device__ __forceinline__ void mma_f16(float* d, const uint32_t* a, const uint32_t* b) {
    asm volatile(
        "mma.sync.aligned.m16n8k16.row.col.f32.f16.f16.f32 "
        "{%0,%1,%2,%3}, {%4,%5,%6,%7}, {%8,%9}, {%0,%1,%2,%3};"
        : "+f"(d[0]), "+f"(d[1]), "+f"(d[2]), "+f"(d[3])
        : "r"(a[0]), "r"(a[1]), "r"(a[2]), "r"(a[3]), "r"(b[0]), "r"(b[1]));
}

// -------- weight transpose + fp16: dst[N][K] = half(src[K][N]) --------
__global__ void tpose_kernel(const float* __restrict__ src, __half* __restrict__ dst,
                             int K, int N)
{
    __shared__ float t[32][33];
    int kb = blockIdx.x << 5, nb = blockIdx.y << 5;
    int tx = threadIdx.x & 31, ty = threadIdx.x >> 5;
    #pragma unroll
    for (int i = 0; i < 32; i += 8)
        t[ty + i][tx] = src[(size_t)(kb + ty + i) * N + nb + tx];
    __syncthreads();
    #pragma unroll
    for (int i = 0; i < 32; i += 8)
        dst[(size_t)(nb + ty + i) * K + kb + tx] = __float2half(t[tx][ty + i]);
}

// ---------------- LayerNorm (warp per row) -> fp16 output ----------------
__global__ void ln_kernel(const float* __restrict__ x, const float* __restrict__ gam,
                          const float* __restrict__ bet, __half* __restrict__ out,
                          int ncols, float eps)
{
    int row  = blockIdx.x * (blockDim.x >> 5) + (threadIdx.x >> 5);
    int lane = threadIdx.x & 31;
    const float4* x4 = (const float4*)(x + (size_t)row * ncols);
    int cnt = (ncols >> 2) >> 5;
    float4 v[6];
    float s = 0.f, s2 = 0.f;
    for (int i = 0; i < cnt; i++) {
        v[i] = x4[lane + (i << 5)];
        s  += v[i].x + v[i].y + v[i].z + v[i].w;
        s2 += v[i].x * v[i].x + v[i].y * v[i].y + v[i].z * v[i].z + v[i].w * v[i].w;
    }
    #pragma unroll
    for (int o = 16; o; o >>= 1) {
        s  += __shfl_xor_sync(0xffffffffu, s,  o);
        s2 += __shfl_xor_sync(0xffffffffu, s2, o);
    }
    float inv_n = 1.f / (float)ncols;
    float mu = s * inv_n;
    float rstd = rsqrtf(fmaxf(s2 * inv_n - mu * mu, 0.f) + eps);
    const float4* g4 = (const float4*)gam;
    const float4* b4 = (const float4*)bet;
    __half2* o2 = (__half2*)(out + (size_t)row * ncols);
    for (int i = 0; i < cnt; i++) {
        float4 gg = g4[lane + (i << 5)], bb = b4[lane + (i << 5)];
        float rx = (v[i].x - mu) * rstd * gg.x + bb.x;
        float ry = (v[i].y - mu) * rstd * gg.y + bb.y;
        float rz = (v[i].z - mu) * rstd * gg.z + bb.z;
        float rw = (v[i].w - mu) * rstd * gg.w + bb.w;
        o2[2 * (lane + (i << 5))]     = __floats2half2_rn(rx, ry);
        o2[2 * (lane + (i << 5)) + 1] = __floats2half2_rn(rz, rw);
    }
}

// -------- depthwise 3x3 conv + silu (half in/out, f32 math) --------
__global__ void conv_silu_kernel(const __half* __restrict__ xz,
                                 const float* __restrict__ cw,
                                 __half* __restrict__ u)
{
    __shared__ float sx[3][32][128];
    int cc = blockIdx.x << 7;
    int h  = blockIdx.y;
    int b  = blockIdx.z;
    int tid = threadIdx.x;
    const __half* base = xz + (size_t)(b << 10) * XZW;

    // 3 rows x 32 w x 128 ch = 12288 halves = 1536 x 16B loads
    for (int i = tid; i < 1536; i += 256) {
        int idx = i << 3;
        int r = idx >> 12;
        int rem = idx & 4095;
        int w = rem >> 7, c = rem & 127;
        int hh = h + r - 1;
        uint4 raw = make_uint4(0u, 0u, 0u, 0u);
        if ((unsigned)hh < 32u)
            raw = *(const uint4*)(base + (size_t)((hh << 5) + w) * XZW + cc + c);
        const __half2* hp = (const __half2*)&raw;
        float* dst = &sx[r][w][c];
        #pragma unroll
        for (int j = 0; j < 4; j++) {
            float2 f = __half22float2(hp[j]);
            dst[2 * j] = f.x; dst[2 * j + 1] = f.y;
        }
    }
    __syncthreads();

    int c  = tid & 127;
    int w0 = tid >> 7;
    float k[9];
    #pragma unroll
    for (int j = 0; j < 9; j++) k[j] = cw[(cc + c) * 9 + j];
    __half* urow = u + (size_t)((b << 10) + (h << 5)) * DI + cc + c;
    #pragma unroll
    for (int i = 0; i < 16; i++) {
        int w = w0 + (i << 1);
        float acc = 0.f;
        #pragma unroll
        for (int kh = 0; kh < 3; kh++)
            #pragma unroll
            for (int kw = 0; kw < 3; kw++) {
                int ww = w + kw - 1;
                if ((unsigned)ww < 32u)
                    acc = fmaf(sx[kh][ww][c], k[kh * 3 + kw], acc);
            }
        urow[(size_t)w * DI] = __float2half(siluf(acc));
    }
}

// ------------- x_dbl = u @ x_proj_w, W^T in smem, 32 tokens/block -------------
__global__ void xdbl_kernel(const __half* __restrict__ u, const float* __restrict__ W,
                            float* __restrict__ xd)
{
    extern __shared__ float sW[];
    int tid = threadIdx.x;
    for (int i = tid; i < 26 * DI; i += 256) {
        int k = i / DI, d = i - k * DI;
        sW[i] = W[(size_t)d * 26 + k];
    }
    __syncthreads();
    int warp = tid >> 5, lane = tid & 31;
    for (int rep = 0; rep < 4; rep++) {
        int tok = blockIdx.x * 32 + rep * 8 + warp;
        const __half* ur = u + (size_t)tok * DI;
        float uc[24];
        #pragma unroll
        for (int i = 0; i < 24; i++) uc[i] = __half2float(ur[lane + 32 * i]);
        #pragma unroll 2
        for (int k = 0; k < 26; k++) {
            float s = 0.f;
            const float* wr = sW + k * DI;
            #pragma unroll
            for (int i = 0; i < 24; i++)
                s = fmaf(uc[i], wr[lane + 32 * i], s);
            #pragma unroll
            for (int o = 16; o; o >>= 1) s += __shfl_xor_sync(0xffffffffu, s, o);
            if (lane == 0) xd[(size_t)tok * 26 + k] = s;
        }
    }
}

// ------------- dt = softplus(xd[:, :24] @ dt_proj_w + b) -> half -------------
__global__ void dt_kernel(const float* __restrict__ xd, const float* __restrict__ dtw,
                          const float* __restrict__ dtb, __half* __restrict__ dto)
{
    int d   = blockIdx.x * 256 + threadIdx.x;
    int tok = blockIdx.y;
    const float* xr = xd + (size_t)tok * 26;
    float s = dtb[d];
    #pragma unroll
    for (int r = 0; r < 24; r++)
        s = fmaf(xr[r], dtw[(size_t)r * DI + d], s);
    dto[(size_t)tok * DI + d] = __float2half(softplusf(s));
}

// --------- selective scan (DS=1) + y epilogue, half I/O ---------
__global__ void scan_kernel(const __half* __restrict__ u, const __half* __restrict__ dt,
                            const float* __restrict__ xd,
                            const float* __restrict__ A_log, const float* __restrict__ Dp,
                            __half* __restrict__ y)
{
    int gwarp = (blockIdx.x * blockDim.x + threadIdx.x) >> 5;
    int lane  = threadIdx.x & 31;
    int b = gwarp / (DI / 32);
    int d = (gwarp % (DI / 32)) * 32 + lane;

    float Aval = -expf(A_log[d]);
    float Dval = Dp[d];

    const __half* up = u  + (size_t)b * LLEN * DI + d;
    const __half* dp = dt + (size_t)b * LLEN * DI + d;
    const float*  xp = xd + (size_t)b * LLEN * 26;
    __half*       yp = y  + (size_t)b * LLEN * DI + d;

    float h = 0.f;
    float uv = __half2float(up[0]), dtv = __half2float(dp[0]);
    float Bc = xp[24], Cc = xp[25];
    for (int l = 0; l < LLEN; l++) {
        float un = 0.f, dn = 0.f, Bn = 0.f, Cn = 0.f;
        if (l + 1 < LLEN) {
            un = __half2float(up[(size_t)(l + 1) * DI]);
            dn = __half2float(dp[(size_t)(l + 1) * DI]);
            Bn = xp[(l + 1) * 26 + 24];
            Cn = xp[(l + 1) * 26 + 25];
        }
        float dA = expf(dtv * Aval);
        h = fmaf(dA, h, dtv * Bc * uv);
        yp[(size_t)l * DI] = __float2half(fmaf(h, Cc, uv * Dval));
        uv = un; dtv = dn; Bc = Bn; Cc = Cn;
    }
}

// ------------- out-norm over DI + gating (half in) -> fp16 out -------------
__global__ void lngate_kernel(const __half* __restrict__ y, const __half* __restrict__ xz,
                              const float* __restrict__ gam, const float* __restrict__ bet,
                              __half* __restrict__ out)
{
    int t    = blockIdx.x * (blockDim.x >> 5) + (threadIdx.x >> 5);
    int lane = threadIdx.x & 31;
    const __half2* y2 = (const __half2*)(y + (size_t)t * DI);
    float2 v[12];
    float s = 0.f, s2 = 0.f;
    #pragma unroll
    for (int i = 0; i < 12; i++) {
        v[i] = __half22float2(y2[lane + (i << 5)]);
        s  += v[i].x + v[i].y;
        s2 += v[i].x * v[i].x + v[i].y * v[i].y;
    }
    #pragma unroll
    for (int o = 16; o; o >>= 1) {
        s  += __shfl_xor_sync(0xffffffffu, s,  o);
        s2 += __shfl_xor_sync(0xffffffffu, s2, o);
    }
    float mu = s * (1.f / DI);
    float rstd = rsqrtf(fmaxf(s2 * (1.f / DI) - mu * mu, 0.f) + 1e-5f);
    const __half2* z2 = (const __half2*)(xz + (size_t)t * XZW + DI);
    const float2* g2 = (const float2*)gam;
    const float2* b2 = (const float2*)bet;
    __half2* o2 = (__half2*)(out + (size_t)t * DI);
    #pragma unroll
    for (int i = 0; i < 12; i++) {
        float2 zz = __half22float2(z2[lane + (i << 5)]);
        float2 gg = g2[lane + (i << 5)], bb = b2[lane + (i << 5)];
        float rx = ((v[i].x - mu) * rstd * gg.x + bb.x) * siluf(zz.x);
        float ry = ((v[i].y - mu) * rstd * gg.y + bb.y) * siluf(zz.y);
        o2[lane + (i << 5)] = __floats2half2_rn(rx, ry);
    }
}

// ===== fp16 TC GEMM with ldmatrix: C[M,N] = A[M,K] @ Bt[N,K]^T, f32 accum =====
// MODE: 0 plain, 1 bias+gelu, 2 bias+resid, 3 resid.  OutT half => half2 stores.
#define GBM 128
#define GBN 128
#define GBK 32
#define STAGES 4
#define HSTR 40                      // halves per smem row (32 + 8 pad); 80B rows
#define ASTG (GBM * HSTR)
#define BSTG (GBN * HSTR)
#define GSMEM (STAGES * (ASTG + BSTG) * 2)   // 81920 bytes

template <int MODE, typename OutT>
__global__ void __launch_bounds__(256, 2)
gemm_f16(const __half* __restrict__ A, const __half* __restrict__ Bt,
         OutT* __restrict__ C, int M, int N, int K,
         const float* __restrict__ bias, const float* __restrict__ resid)
{
    extern __shared__ __half sh[];
    __half* As = sh;
    __half* Bs = sh + STAGES * ASTG;

    int bm = blockIdx.y * GBM, bn = blockIdx.x * GBN;
    int tid = threadIdx.x;
    int warp = tid >> 5, lane = tid & 31;
    int wm = warp >> 2, wn = warp & 3;      // 2x4 warps: 64x32 per warp
    int g = lane >> 2, t = lane & 3;

    int rowi[2], chk[2];
    #pragma unroll
    for (int i = 0; i < 2; i++) {
        int f = tid + i * 256;
        rowi[i] = f >> 2;
        chk[i]  = (f & 3) << 3;
    }

    auto load_stage = [&](int s, int k0) {
        __half* Ad = As + s * ASTG;
        __half* Bd = Bs + s * BSTG;
        #pragma unroll
        for (int i = 0; i < 2; i++) {
            cp_async16(smem_u32(&Ad[rowi[i] * HSTR + chk[i]]),
                       A + (size_t)(bm + rowi[i]) * K + k0 + chk[i]);
            cp_async16(smem_u32(&Bd[rowi[i] * HSTR + chk[i]]),
                       Bt + (size_t)(bn + rowi[i]) * K + k0 + chk[i]);
        }
        cp_commit();
    };

    int nIter = K / GBK;
    #pragma unroll
    for (int s = 0; s < STAGES - 1; s++) load_stage(s, s * GBK);

    float acc[4][4][4];
    #pragma unroll
    for (int i = 0; i < 4; i++)
        #pragma unroll
        for (int j = 0; j < 4; j++)
            #pragma unroll
            for (int r = 0; r < 4; r++) acc[i][j][r] = 0.f;

    // ldmatrix lane geometry
    int asel = lane >> 3;                    // 0..3
    int a_r  = (asel & 1) * 8 + (lane & 7);  // row offset within 16
    int a_c  = (asel >> 1) * 8;              // k offset within 16
    int b_r  = lane & 7;
    int b_c  = ((lane >> 3) & 1) * 8;

    for (int it = 0; it < nIter; it++) {
        cp_wait<STAGES - 2>();
        __syncthreads();
        int pf = it + STAGES - 1;
        if (pf < nIter) load_stage(pf % STAGES, pf * GBK);
        else            cp_commit();

        const __half* Ab = As + (it % STAGES) * ASTG;
        const __half* Bb = Bs + (it % STAGES) * BSTG;
        #pragma unroll
        for (int ks = 0; ks < 2; ks++) {
            int kb = ks * 16;
            uint32_t af[4][4], bf[4][2];
            #pragma unroll
            for (int mi = 0; mi < 4; mi++) {
                uint32_t ad = smem_u32(&Ab[(wm * 64 + mi * 16 + a_r) * HSTR + kb + a_c]);
                asm volatile(
                    "ldmatrix.sync.aligned.m8n8.x4.shared.b16 {%0,%1,%2,%3}, [%4];"
                    : "=r"(af[mi][0]), "=r"(af[mi][1]), "=r"(af[mi][2]), "=r"(af[mi][3])
                    : "r"(ad));
            }
            #pragma unroll
            for (int ni = 0; ni < 4; ni++) {
                uint32_t bd = smem_u32(&Bb[(wn * 32 + ni * 8 + b_r) * HSTR + kb + b_c]);
                asm volatile(
                    "ldmatrix.sync.aligned.m8n8.x2.shared.b16 {%0,%1}, [%2];"
                    : "=r"(bf[ni][0]), "=r"(bf[ni][1])
                    : "r"(bd));
            }
            #pragma unroll
            for (int mi = 0; mi < 4; mi++)
                #pragma unroll
                for (int ni = 0; ni < 4; ni++)
                    mma_f16(acc[mi][ni], af[mi], bf[ni]);
        }
    }

    // epilogue
    #pragma unroll
    for (int mi = 0; mi < 4; mi++) {
        #pragma unroll
        for (int half_ = 0; half_ < 2; half_++) {
            int row = bm + wm * 64 + mi * 16 + g + half_ * 8;
            #pragma unroll
            for (int ni = 0; ni < 4; ni++) {
                int col = bn + wn * 32 + ni * 8 + 2 * t;
                float v0 = acc[mi][ni][half_ * 2 + 0];
                float v1 = acc[mi][ni][half_ * 2 + 1];
                if (MODE == 1) {
                    float2 bb = *(const float2*)(bias + col);
                    v0 = geluf(v0 + bb.x); v1 = geluf(v1 + bb.y);
                } else if (MODE == 2) {
                    float2 bb = *(const float2*)(bias + col);
                    float2 rs = *(const float2*)(resid + (size_t)row * N + col);
                    v0 += bb.x + rs.x; v1 += bb.y + rs.y;
                } else if (MODE == 3) {
                    float2 rs = *(const float2*)(resid + (size_t)row * N + col);
                    v0 += rs.x; v1 += rs.y;
                }
                if (sizeof(OutT) == 2) {
                    *(__half2*)((__half*)C + (size_t)row * N + col) =
                        __floats2half2_rn(v0, v1);
                } else {
                    *(float2*)((float*)C + (size_t)row * N + col) = make_float2(v0, v1);
                }
            }
        }
    }
}

// ---------------- launch ----------------
extern "C" void kernel_launch(void* const* d_in, const int* in_sizes, int n_in,
                              void* d_out, int out_size)
{
    const float* x        = (const float*)d_in[0];
    const float* ln1_g    = (const float*)d_in[1];
    const float* ln1_b    = (const float*)d_in[2];
    const float* w_in     = (const float*)d_in[3];
    const float* conv_w   = (const float*)d_in[4];
    const float* x_proj_w = (const float*)d_in[5];
    const float* dt_w     = (const float*)d_in[6];
    const float* dt_b     = (const float*)d_in[7];
    const float* A_log    = (const float*)d_in[8];
    const float* Dp       = (const float*)d_in[9];
    const float* on_g     = (const float*)d_in[10];
    const float* on_b     = (const float*)d_in[11];
    const float* w_out    = (const float*)d_in[12];
    const float* ln2_g    = (const float*)d_in[13];
    const float* ln2_b    = (const float*)d_in[14];
    const float* fc1_w    = (const float*)d_in[15];
    const float* fc1_b    = (const float*)d_in[16];
    const float* fc2_w    = (const float*)d_in[17];
    const float* fc2_b    = (const float*)d_in[18];
    float* out = (float*)d_out;

    __half *h1, *xz, *u, *dt, *y, *g, *h2, *hid, *wr;
    float *xd, *x1;
    cudaGetSymbolAddress((void**)&h1,  g_h1);
    cudaGetSymbolAddress((void**)&xz,  g_xz);
    cudaGetSymbolAddress((void**)&u,   g_u);
    cudaGetSymbolAddress((void**)&xd,  g_xd);
    cudaGetSymbolAddress((void**)&dt,  g_dt);
    cudaGetSymbolAddress((void**)&y,   g_y);
    cudaGetSymbolAddress((void**)&g,   g_g);
    cudaGetSymbolAddress((void**)&x1,  g_x1);
    cudaGetSymbolAddress((void**)&h2,  g_h2);
    cudaGetSymbolAddress((void**)&hid, g_hid);
    cudaGetSymbolAddress((void**)&wr,  g_wr);

    cudaFuncSetAttribute(gemm_f16<0, __half>, cudaFuncAttributeMaxDynamicSharedMemorySize, GSMEM);
    cudaFuncSetAttribute(gemm_f16<1, __half>, cudaFuncAttributeMaxDynamicSharedMemorySize, GSMEM);
    cudaFuncSetAttribute(gemm_f16<2, float >, cudaFuncAttributeMaxDynamicSharedMemorySize, GSMEM);
    cudaFuncSetAttribute(gemm_f16<3, float >, cudaFuncAttributeMaxDynamicSharedMemorySize, GSMEM);
    cudaFuncSetAttribute(xdbl_kernel, cudaFuncAttributeMaxDynamicSharedMemorySize, 26 * DI * 4);

    // 0. transpose + fp16 weights: [K,N] -> [N,K]
    tpose_kernel<<<dim3(CDIM / 32, XZW / 32), 256>>>(w_in,  wr + WR_WIN,  CDIM, XZW);
    tpose_kernel<<<dim3(DI / 32, CDIM / 32), 256>>>(w_out, wr + WR_WOUT, DI, CDIM);
    tpose_kernel<<<dim3(CDIM / 32, HIDD / 32), 256>>>(fc1_w, wr + WR_FC1, CDIM, HIDD);
    tpose_kernel<<<dim3(HIDD / 32, CDIM / 32), 256>>>(fc2_w, wr + WR_FC2, HIDD, CDIM);

    // 1. h1 = LN(x) -> fp16
    ln_kernel<<<NTOK / 8, 256>>>(x, ln1_g, ln1_b, h1, CDIM, 1e-6f);
    // 2. xz = h1 @ w_in  (half out)
    gemm_f16<0, __half><<<dim3(XZW / GBN, NTOK / GBM), 256, GSMEM>>>(
        h1, wr + WR_WIN, xz, NTOK, XZW, CDIM, nullptr, nullptr);
    // 3. u = silu(dwconv3x3(xm))  (half)
    conv_silu_kernel<<<dim3(DI / 128, 32, NBAT), 256>>>(xz, conv_w, u);
    // 4. x_dbl = u @ x_proj_w
    xdbl_kernel<<<NTOK / 32, 256, 26 * DI * 4>>>(u, x_proj_w, xd);
    // 5. dt (half)
    dt_kernel<<<dim3(DI / 256, NTOK), 256>>>(xd, dt_w, dt_b, dt);
    // 6. scan (half I/O)
    scan_kernel<<<(NBAT * (DI / 32) * 32) / 256, 256>>>(u, dt, xd, A_log, Dp, y);
    // 7. g = LN_out(y) * silu(z) -> fp16
    lngate_kernel<<<NTOK / 8, 256>>>(y, xz, on_g, on_b, g);
    // 8. x1 = g @ w_out + x  (f32 out)
    gemm_f16<3, float><<<dim3(CDIM / GBN, NTOK / GBM), 256, GSMEM>>>(
        g, wr + WR_WOUT, x1, NTOK, CDIM, DI, nullptr, x);
    // 9. h2 = LN(x1) -> fp16
    ln_kernel<<<NTOK / 8, 256>>>(x1, ln2_g, ln2_b, h2, CDIM, 1e-6f);
    // 10. hid = gelu(h2 @ fc1_w + fc1_b) -> fp16
    gemm_f16<1, __half><<<dim3(HIDD / GBN, NTOK / GBM), 256, GSMEM>>>(
        h2, wr + WR_FC1, hid, NTOK, HIDD, CDIM, fc1_b, nullptr);
    // 11. out = hid @ fc2_w + fc2_b + x1  (f32 out)
    gemm_f16<2, float><<<dim3(CDIM / GBN, NTOK / GBM), 256, GSMEM>>>(
        hid, wr + WR_FC2, out, NTOK, CDIM, HIDD, fc2_b, x1);
}

// round 14
// speedup vs baseline: 3.3108x; 1.1540x over previous
#include <cuda_runtime.h>
#include <cuda_fp16.h>
#include <math.h>
#include <stdint.h>

#define NTOK 16384
#define CDIM 384
#define DI   768
#define LLEN 1024
#define NBAT 16
#define HIDD 1536
#define XZW  1536   // 2*DI

// ---------------- scratch (device globals) ----------------
__device__ __half g_h1 [NTOK * CDIM];
__device__ __half g_xz [NTOK * XZW];
__device__ __half g_u  [NTOK * DI];
__device__ __half g_xdh[NTOK * 64 + 512];   // padded for pipeline over-read
__device__ __half g_dt [NTOK * DI];
__device__ __half g_y  [NTOK * DI];
__device__ __half g_g  [NTOK * DI];
__device__ float  g_x1 [NTOK * CDIM];
__device__ __half g_h2 [NTOK * CDIM];
__device__ __half g_hid[NTOK * HIDD];
// fp16 transposed weights ([N][K] K-major): w_in | w_out | fc1 | fc2 | xprojT | dtwT
#define WR_WIN  0
#define WR_WOUT (CDIM * XZW)
#define WR_FC1  (WR_WOUT + DI * CDIM)
#define WR_FC2  (WR_FC1 + CDIM * HIDD)
#define WR_XP   (WR_FC2 + HIDD * CDIM)
#define WR_DTW  (WR_XP + 64 * DI)
__device__ __half g_wr [WR_DTW + DI * 64 + 512];   // padded for over-read

// ---------------- helpers ----------------
__device__ __forceinline__ float siluf(float x) { return x / (1.f + expf(-x)); }
__device__ __forceinline__ float geluf(float x) {
    float x3 = x * x * x;
    return 0.5f * x * (1.f + tanhf(0.7978845608028654f * (x + 0.044715f * x3)));
}
__device__ __forceinline__ float softplusf(float x) {
    return (x > 20.f) ? x : log1pf(expf(x));
}
__device__ __forceinline__ uint32_t smem_u32(const void* p) {
    return (uint32_t)__cvta_generic_to_shared(p);
}
__device__ __forceinline__ void cp_async16(uint32_t dst, const void* src) {
    asm volatile("cp.async.ca.shared.global [%0], [%1], 16;" :: "r"(dst), "l"(src));
}
__device__ __forceinline__ void cp_commit() { asm volatile("cp.async.commit_group;"); }
template <int N>
__device__ __forceinline__ void cp_wait() {
    asm volatile("cp.async.wait_group %0;" :: "n"(N));
}
__device__ __forceinline__ void mma_f16(float* d, const uint32_t* a, const uint32_t* b) {
    asm volatile(
        "mma.sync.aligned.m16n8k16.row.col.f32.f16.f16.f32 "
        "{%0,%1,%2,%3}, {%4,%5,%6,%7}, {%8,%9}, {%0,%1,%2,%3};"
        : "+f"(d[0]), "+f"(d[1]), "+f"(d[2]), "+f"(d[3])
        : "r"(a[0]), "r"(a[1]), "r"(a[2]), "r"(a[3]), "r"(b[0]), "r"(b[1]));
}

// -------- weight transpose + fp16: dst[N][K] = half(src[K][N]) --------
__global__ void tpose_kernel(const float* __restrict__ src, __half* __restrict__ dst,
                             int K, int N)
{
    __shared__ float t[32][33];
    int kb = blockIdx.x << 5, nb = blockIdx.y << 5;
    int tx = threadIdx.x & 31, ty = threadIdx.x >> 5;
    #pragma unroll
    for (int i = 0; i < 32; i += 8)
        t[ty + i][tx] = src[(size_t)(kb + ty + i) * N + nb + tx];
    __syncthreads();
    #pragma unroll
    for (int i = 0; i < 32; i += 8)
        dst[(size_t)(nb + ty + i) * K + kb + tx] = __float2half(t[tx][ty + i]);
}

// xprojT[n][k] = n<26 ? x_proj_w[k][n] : 0     (64 x 768)
__global__ void xprojT_kernel(const float* __restrict__ W, __half* __restrict__ dst)
{
    int k = blockIdx.x * 256 + threadIdx.x;   // 0..767
    int n = blockIdx.y;                        // 0..63
    dst[n * DI + k] = __float2half(n < 26 ? W[(size_t)k * 26 + n] : 0.f);
}

// dtwT[d][r] = r<24 ? dt_proj_w[r][d] : 0     (768 x 64)
__global__ void dtwT_kernel(const float* __restrict__ W, __half* __restrict__ dst)
{
    int i = blockIdx.x * 256 + threadIdx.x;   // over 768*64
    int d = i >> 6, r = i & 63;
    dst[i] = __float2half(r < 24 ? W[(size_t)r * DI + d] : 0.f);
}

// ---------------- LayerNorm (warp per row) -> fp16 output ----------------
__global__ void ln_kernel(const float* __restrict__ x, const float* __restrict__ gam,
                          const float* __restrict__ bet, __half* __restrict__ out,
                          int ncols, float eps)
{
    int row  = blockIdx.x * (blockDim.x >> 5) + (threadIdx.x >> 5);
    int lane = threadIdx.x & 31;
    const float4* x4 = (const float4*)(x + (size_t)row * ncols);
    int cnt = (ncols >> 2) >> 5;
    float4 v[6];
    float s = 0.f, s2 = 0.f;
    for (int i = 0; i < cnt; i++) {
        v[i] = x4[lane + (i << 5)];
        s  += v[i].x + v[i].y + v[i].z + v[i].w;
        s2 += v[i].x * v[i].x + v[i].y * v[i].y + v[i].z * v[i].z + v[i].w * v[i].w;
    }
    #pragma unroll
    for (int o = 16; o; o >>= 1) {
        s  += __shfl_xor_sync(0xffffffffu, s,  o);
        s2 += __shfl_xor_sync(0xffffffffu, s2, o);
    }
    float inv_n = 1.f / (float)ncols;
    float mu = s * inv_n;
    float rstd = rsqrtf(fmaxf(s2 * inv_n - mu * mu, 0.f) + eps);
    const float4* g4 = (const float4*)gam;
    const float4* b4 = (const float4*)bet;
    __half2* o2 = (__half2*)(out + (size_t)row * ncols);
    for (int i = 0; i < cnt; i++) {
        float4 gg = g4[lane + (i << 5)], bb = b4[lane + (i << 5)];
        float rx = (v[i].x - mu) * rstd * gg.x + bb.x;
        float ry = (v[i].y - mu) * rstd * gg.y + bb.y;
        float rz = (v[i].z - mu) * rstd * gg.z + bb.z;
        float rw = (v[i].w - mu) * rstd * gg.w + bb.w;
        o2[2 * (lane + (i << 5))]     = __floats2half2_rn(rx, ry);
        o2[2 * (lane + (i << 5)) + 1] = __floats2half2_rn(rz, rw);
    }
}

// -------- depthwise 3x3 conv + silu (half in/out, f32 math) --------
__global__ void conv_silu_kernel(const __half* __restrict__ xz,
                                 const float* __restrict__ cw,
                                 __half* __restrict__ u)
{
    __shared__ float sx[3][32][128];
    int cc = blockIdx.x << 7;
    int h  = blockIdx.y;
    int b  = blockIdx.z;
    int tid = threadIdx.x;
    const __half* base = xz + (size_t)(b << 10) * XZW;

    for (int i = tid; i < 1536; i += 256) {
        int idx = i << 3;
        int r = idx >> 12;
        int rem = idx & 4095;
        int w = rem >> 7, c = rem & 127;
        int hh = h + r - 1;
        uint4 raw = make_uint4(0u, 0u, 0u, 0u);
        if ((unsigned)hh < 32u)
            raw = *(const uint4*)(base + (size_t)((hh << 5) + w) * XZW + cc + c);
        const __half2* hp = (const __half2*)&raw;
        float* dst = &sx[r][w][c];
        #pragma unroll
        for (int j = 0; j < 4; j++) {
            float2 f = __half22float2(hp[j]);
            dst[2 * j] = f.x; dst[2 * j + 1] = f.y;
        }
    }
    __syncthreads();

    int c  = tid & 127;
    int w0 = tid >> 7;
    float k[9];
    #pragma unroll
    for (int j = 0; j < 9; j++) k[j] = cw[(cc + c) * 9 + j];
    __half* urow = u + (size_t)((b << 10) + (h << 5)) * DI + cc + c;
    #pragma unroll
    for (int i = 0; i < 16; i++) {
        int w = w0 + (i << 1);
        float acc = 0.f;
        #pragma unroll
        for (int kh = 0; kh < 3; kh++)
            #pragma unroll
            for (int kw = 0; kw < 3; kw++) {
                int ww = w + kw - 1;
                if ((unsigned)ww < 32u)
                    acc = fmaf(sx[kh][ww][c], k[kh * 3 + kw], acc);
            }
        urow[(size_t)w * DI] = __float2half(siluf(acc));
    }
}

// --------- selective scan (DS=1) + y epilogue, half I/O ---------
__global__ void scan_kernel(const __half* __restrict__ u, const __half* __restrict__ dt,
                            const __half* __restrict__ xdh,
                            const float* __restrict__ A_log, const float* __restrict__ Dp,
                            __half* __restrict__ y)
{
    int gwarp = (blockIdx.x * blockDim.x + threadIdx.x) >> 5;
    int lane  = threadIdx.x & 31;
    int b = gwarp / (DI / 32);
    int d = (gwarp % (DI / 32)) * 32 + lane;

    float Aval = -expf(A_log[d]);
    float Dval = Dp[d];

    const __half* up = u   + (size_t)b * LLEN * DI + d;
    const __half* dp = dt  + (size_t)b * LLEN * DI + d;
    const __half* xp = xdh + (size_t)b * LLEN * 64;
    __half*       yp = y   + (size_t)b * LLEN * DI + d;

    float h = 0.f;
    float uv = __half2float(up[0]), dtv = __half2float(dp[0]);
    float2 bc = __half22float2(*(const __half2*)(xp + 24));
    float Bc = bc.x, Cc = bc.y;
    for (int l = 0; l < LLEN; l++) {
        float un = 0.f, dn = 0.f, Bn = 0.f, Cn = 0.f;
        if (l + 1 < LLEN) {
            un = __half2float(up[(size_t)(l + 1) * DI]);
            dn = __half2float(dp[(size_t)(l + 1) * DI]);
            float2 b2 = __half22float2(*(const __half2*)(xp + (l + 1) * 64 + 24));
            Bn = b2.x; Cn = b2.y;
        }
        float dA = expf(dtv * Aval);
        h = fmaf(dA, h, dtv * Bc * uv);
        yp[(size_t)l * DI] = __float2half(fmaf(h, Cc, uv * Dval));
        uv = un; dtv = dn; Bc = Bn; Cc = Cn;
    }
}

// ------------- out-norm over DI + gating (half in) -> fp16 out -------------
__global__ void lngate_kernel(const __half* __restrict__ y, const __half* __restrict__ xz,
                              const float* __restrict__ gam, const float* __restrict__ bet,
                              __half* __restrict__ out)
{
    int t    = blockIdx.x * (blockDim.x >> 5) + (threadIdx.x >> 5);
    int lane = threadIdx.x & 31;
    const __half2* y2 = (const __half2*)(y + (size_t)t * DI);
    float2 v[12];
    float s = 0.f, s2 = 0.f;
    #pragma unroll
    for (int i = 0; i < 12; i++) {
        v[i] = __half22float2(y2[lane + (i << 5)]);
        s  += v[i].x + v[i].y;
        s2 += v[i].x * v[i].x + v[i].y * v[i].y;
    }
    #pragma unroll
    for (int o = 16; o; o >>= 1) {
        s  += __shfl_xor_sync(0xffffffffu, s,  o);
        s2 += __shfl_xor_sync(0xffffffffu, s2, o);
    }
    float mu = s * (1.f / DI);
    float rstd = rsqrtf(fmaxf(s2 * (1.f / DI) - mu * mu, 0.f) + 1e-5f);
    const __half2* z2 = (const __half2*)(xz + (size_t)t * XZW + DI);
    const float2* g2 = (const float2*)gam;
    const float2* b2 = (const float2*)bet;
    __half2* o2 = (__half2*)(out + (size_t)t * DI);
    #pragma unroll
    for (int i = 0; i < 12; i++) {
        float2 zz = __half22float2(z2[lane + (i << 5)]);
        float2 gg = g2[lane + (i << 5)], bb = b2[lane + (i << 5)];
        float rx = ((v[i].x - mu) * rstd * gg.x + bb.x) * siluf(zz.x);
        float ry = ((v[i].y - mu) * rstd * gg.y + bb.y) * siluf(zz.y);
        o2[lane + (i << 5)] = __floats2half2_rn(rx, ry);
    }
}

// ===== fp16 TC GEMM (ldmatrix): C[M,N] = A[M,K] @ Bt[N,K]^T, f32 accum =====
// MODE: 0 plain, 1 bias+gelu, 2 bias+resid, 3 resid, 4 bias+softplus
// Tile: GBM=128 x GBN_ (template), warp grid WM x WN (8 warps)
#define GBM 128
#define GBK 32
#define STAGES 4
#define HSTR 40                      // halves per smem row (32 + 8 pad)
constexpr int t5smem(int gbn) { return STAGES * (GBM + gbn) * HSTR * 2; }

template <int MODE, typename OutT, int GBN_, int WM, int WN>
__global__ void __launch_bounds__(256, 2)
gemm_f16(const __half* __restrict__ A, const __half* __restrict__ Bt,
         OutT* __restrict__ C, int M, int N, int K,
         const float* __restrict__ bias, const float* __restrict__ resid)
{
    constexpr int MI = GBM / (WM * 16);
    constexpr int NI = GBN_ / (WN * 8);
    constexpr int ASTG_ = GBM * HSTR;
    constexpr int BSTG_ = GBN_ * HSTR;
    constexpr int ACH = GBM / 64;     // 16B chunks per thread for A
    constexpr int BCH = GBN_ / 64;

    extern __shared__ __half sh[];
    __half* As = sh;
    __half* Bs = sh + STAGES * ASTG_;

    int bm = blockIdx.y * GBM, bn = blockIdx.x * GBN_;
    int tid = threadIdx.x;
    int warp = tid >> 5, lane = tid & 31;
    int wm = warp / WN, wn = warp % WN;
    int g = lane >> 2, t = lane & 3;

    int arow[ACH], acol[ACH], brow[BCH], bcol[BCH];
    #pragma unroll
    for (int i = 0; i < ACH; i++) {
        int f = tid + i * 256;
        arow[i] = f >> 2; acol[i] = (f & 3) << 3;
    }
    #pragma unroll
    for (int i = 0; i < BCH; i++) {
        int f = tid + i * 256;
        brow[i] = f >> 2; bcol[i] = (f & 3) << 3;
    }

    auto load_stage = [&](int s, int k0) {
        __half* Ad = As + s * ASTG_;
        __half* Bd = Bs + s * BSTG_;
        #pragma unroll
        for (int i = 0; i < ACH; i++)
            cp_async16(smem_u32(&Ad[arow[i] * HSTR + acol[i]]),
                       A + (size_t)(bm + arow[i]) * K + k0 + acol[i]);
        #pragma unroll
        for (int i = 0; i < BCH; i++)
            cp_async16(smem_u32(&Bd[brow[i] * HSTR + bcol[i]]),
                       Bt + (size_t)(bn + brow[i]) * K + k0 + bcol[i]);
        cp_commit();
    };

    int nIter = K / GBK;
    #pragma unroll
    for (int s = 0; s < STAGES - 1; s++) load_stage(s, s * GBK);

    float acc[MI][NI][4];
    #pragma unroll
    for (int i = 0; i < MI; i++)
        #pragma unroll
        for (int j = 0; j < NI; j++)
            #pragma unroll
            for (int r = 0; r < 4; r++) acc[i][j][r] = 0.f;

    // ldmatrix lane geometry
    int asel = lane >> 3;
    int a_r  = (asel & 1) * 8 + (lane & 7);
    int a_c  = (asel >> 1) * 8;
    int b_r  = lane & 7;
    int b_c  = ((lane >> 3) & 1) * 8;

    for (int it = 0; it < nIter; it++) {
        cp_wait<STAGES - 2>();
        __syncthreads();
        int pf = it + STAGES - 1;
        if (pf < nIter) load_stage(pf % STAGES, pf * GBK);
        else            cp_commit();

        const __half* Ab = As + (it % STAGES) * ASTG_;
        const __half* Bb = Bs + (it % STAGES) * BSTG_;
        #pragma unroll
        for (int ks = 0; ks < 2; ks++) {
            int kb = ks * 16;
            uint32_t af[MI][4], bf[NI][2];
            #pragma unroll
            for (int mi = 0; mi < MI; mi++) {
                uint32_t ad = smem_u32(&Ab[(wm * (MI * 16) + mi * 16 + a_r) * HSTR + kb + a_c]);
                asm volatile(
                    "ldmatrix.sync.aligned.m8n8.x4.shared.b16 {%0,%1,%2,%3}, [%4];"
                    : "=r"(af[mi][0]), "=r"(af[mi][1]), "=r"(af[mi][2]), "=r"(af[mi][3])
                    : "r"(ad));
            }
            #pragma unroll
            for (int ni = 0; ni < NI; ni++) {
                uint32_t bd = smem_u32(&Bb[(wn * (NI * 8) + ni * 8 + b_r) * HSTR + kb + b_c]);
                asm volatile(
                    "ldmatrix.sync.aligned.m8n8.x2.shared.b16 {%0,%1}, [%2];"
                    : "=r"(bf[ni][0]), "=r"(bf[ni][1])
                    : "r"(bd));
            }
            #pragma unroll
            for (int mi = 0; mi < MI; mi++)
                #pragma unroll
                for (int ni = 0; ni < NI; ni++)
                    mma_f16(acc[mi][ni], af[mi], bf[ni]);
        }
    }

    // epilogue
    #pragma unroll
    for (int mi = 0; mi < MI; mi++) {
        #pragma unroll
        for (int half_ = 0; half_ < 2; half_++) {
            int row = bm + wm * (MI * 16) + mi * 16 + g + half_ * 8;
            #pragma unroll
            for (int ni = 0; ni < NI; ni++) {
                int col = bn + wn * (NI * 8) + ni * 8 + 2 * t;
                float v0 = acc[mi][ni][half_ * 2 + 0];
                float v1 = acc[mi][ni][half_ * 2 + 1];
                if (MODE == 1) {
                    float2 bb = *(const float2*)(bias + col);
                    v0 = geluf(v0 + bb.x); v1 = geluf(v1 + bb.y);
                } else if (MODE == 2) {
                    float2 bb = *(const float2*)(bias + col);
                    float2 rs = *(const float2*)(resid + (size_t)row * N + col);
                    v0 += bb.x + rs.x; v1 += bb.y + rs.y;
                } else if (MODE == 3) {
                    float2 rs = *(const float2*)(resid + (size_t)row * N + col);
                    v0 += rs.x; v1 += rs.y;
                } else if (MODE == 4) {
                    float2 bb = *(const float2*)(bias + col);
                    v0 = softplusf(v0 + bb.x); v1 = softplusf(v1 + bb.y);
                }
                if (sizeof(OutT) == 2) {
                    *(__half2*)((__half*)C + (size_t)row * N + col) =
                        __floats2half2_rn(v0, v1);
                } else {
                    *(float2*)((float*)C + (size_t)row * N + col) = make_float2(v0, v1);
                }
            }
        }
    }
}

// ---------------- launch ----------------
extern "C" void kernel_launch(void* const* d_in, const int* in_sizes, int n_in,
                              void* d_out, int out_size)
{
    const float* x        = (const float*)d_in[0];
    const float* ln1_g    = (const float*)d_in[1];
    const float* ln1_b    = (const float*)d_in[2];
    const float* w_in     = (const float*)d_in[3];
    const float* conv_w   = (const float*)d_in[4];
    const float* x_proj_w = (const float*)d_in[5];
    const float* dt_w     = (const float*)d_in[6];
    const float* dt_b     = (const float*)d_in[7];
    const float* A_log    = (const float*)d_in[8];
    const float* Dp       = (const float*)d_in[9];
    const float* on_g     = (const float*)d_in[10];
    const float* on_b     = (const float*)d_in[11];
    const float* w_out    = (const float*)d_in[12];
    const float* ln2_g    = (const float*)d_in[13];
    const float* ln2_b    = (const float*)d_in[14];
    const float* fc1_w    = (const float*)d_in[15];
    const float* fc1_b    = (const float*)d_in[16];
    const float* fc2_w    = (const float*)d_in[17];
    const float* fc2_b    = (const float*)d_in[18];
    float* out = (float*)d_out;

    __half *h1, *xz, *u, *xdh, *dt, *y, *g, *h2, *hid, *wr;
    float *x1;
    cudaGetSymbolAddress((void**)&h1,  g_h1);
    cudaGetSymbolAddress((void**)&xz,  g_xz);
    cudaGetSymbolAddress((void**)&u,   g_u);
    cudaGetSymbolAddress((void**)&xdh, g_xdh);
    cudaGetSymbolAddress((void**)&dt,  g_dt);
    cudaGetSymbolAddress((void**)&y,   g_y);
    cudaGetSymbolAddress((void**)&g,   g_g);
    cudaGetSymbolAddress((void**)&x1,  g_x1);
    cudaGetSymbolAddress((void**)&h2,  g_h2);
    cudaGetSymbolAddress((void**)&hid, g_hid);
    cudaGetSymbolAddress((void**)&wr,  g_wr);

    cudaFuncSetAttribute((void*)gemm_f16<0, __half, 128, 2, 4>, cudaFuncAttributeMaxDynamicSharedMemorySize, t5smem(128));
    cudaFuncSetAttribute((void*)gemm_f16<1, __half, 128, 2, 4>, cudaFuncAttributeMaxDynamicSharedMemorySize, t5smem(128));
    cudaFuncSetAttribute((void*)gemm_f16<4, __half, 128, 2, 4>, cudaFuncAttributeMaxDynamicSharedMemorySize, t5smem(128));
    cudaFuncSetAttribute((void*)gemm_f16<0, __half, 64, 4, 2>,  cudaFuncAttributeMaxDynamicSharedMemorySize, t5smem(64));
    cudaFuncSetAttribute((void*)gemm_f16<2, float, 64, 4, 2>,   cudaFuncAttributeMaxDynamicSharedMemorySize, t5smem(64));
    cudaFuncSetAttribute((void*)gemm_f16<3, float, 64, 4, 2>,   cudaFuncAttributeMaxDynamicSharedMemorySize, t5smem(64));

    // 0. weight prep: transposed fp16 copies (+ zero-padded small projections)
    tpose_kernel<<<dim3(CDIM / 32, XZW / 32), 256>>>(w_in,  wr + WR_WIN,  CDIM, XZW);
    tpose_kernel<<<dim3(DI / 32, CDIM / 32), 256>>>(w_out, wr + WR_WOUT, DI, CDIM);
    tpose_kernel<<<dim3(CDIM / 32, HIDD / 32), 256>>>(fc1_w, wr + WR_FC1, CDIM, HIDD);
    tpose_kernel<<<dim3(HIDD / 32, CDIM / 32), 256>>>(fc2_w, wr + WR_FC2, HIDD, CDIM);
    xprojT_kernel<<<dim3(3, 64), 256>>>(x_proj_w, wr + WR_XP);
    dtwT_kernel<<<192, 256>>>(dt_w, wr + WR_DTW);

    // 1. h1 = LN(x) -> fp16
    ln_kernel<<<NTOK / 8, 256>>>(x, ln1_g, ln1_b, h1, CDIM, 1e-6f);
    // 2. xz = h1 @ w_in  (half out)
    gemm_f16<0, __half, 128, 2, 4><<<dim3(XZW / 128, NTOK / GBM), 256, t5smem(128)>>>(
        h1, wr + WR_WIN, xz, NTOK, XZW, CDIM, nullptr, nullptr);
    // 3. u = silu(dwconv3x3(xm))  (half)
    conv_silu_kernel<<<dim3(DI / 128, 32, NBAT), 256>>>(xz, conv_w, u);
    // 4. xd = u @ xprojT^T  (16384 x 64, K=768; cols 26..63 are zero)
    gemm_f16<0, __half, 64, 4, 2><<<dim3(1, NTOK / GBM), 256, t5smem(64)>>>(
        u, wr + WR_XP, xdh, NTOK, 64, DI, nullptr, nullptr);
    // 5. dt = softplus(xd @ dtwT^T + dtb)  (16384 x 768, K=64)
    gemm_f16<4, __half, 128, 2, 4><<<dim3(DI / 128, NTOK / GBM), 256, t5smem(128)>>>(
        xdh, wr + WR_DTW, dt, NTOK, DI, 64, dt_b, nullptr);
    // 6. scan (half I/O, B/C from xd)
    scan_kernel<<<(NBAT * (DI / 32) * 32) / 256, 256>>>(u, dt, xdh, A_log, Dp, y);
    // 7. g = LN_out(y) * silu(z) -> fp16
    lngate_kernel<<<NTOK / 8, 256>>>(y, xz, on_g, on_b, g);
    // 8. x1 = g @ w_out + x  (f32 out, N=384 via 64-wide tiles)
    gemm_f16<3, float, 64, 4, 2><<<dim3(CDIM / 64, NTOK / GBM), 256, t5smem(64)>>>(
        g, wr + WR_WOUT, x1, NTOK, CDIM, DI, nullptr, x);
    // 9. h2 = LN(x1) -> fp16
    ln_kernel<<<NTOK / 8, 256>>>(x1, ln2_g, ln2_b, h2, CDIM, 1e-6f);
    // 10. hid = gelu(h2 @ fc1_w + fc1_b) -> fp16
    gemm_f16<1, __half, 128, 2, 4><<<dim3(HIDD / 128, NTOK / GBM), 256, t5smem(128)>>>(
        h2, wr + WR_FC1, hid, NTOK, HIDD, CDIM, fc1_b, nullptr);
    // 11. out = hid @ fc2_w + fc2_b + x1  (f32 out, N=384 via 64-wide tiles)
    gemm_f16<2, float, 64, 4, 2><<<dim3(CDIM / 64, NTOK / GBM), 256, t5smem(64)>>>(
        hid, wr + WR_FC2, out, NTOK, CDIM, HIDD, fc2_b, x1);
}

// round 15
// speedup vs baseline: 4.5759x; 1.3821x over previous
#include <cuda_runtime.h>
#include <cuda_fp16.h>
#include <math.h>
#include <stdint.h>

#define NTOK 16384
#define CDIM 384
#define DI   768
#define LLEN 1024
#define NBAT 16
#define HIDD 1536
#define XZW  1536   // 2*DI
#define NCHUNK 8
#define CLEN   128   // LLEN / NCHUNK

// ---------------- scratch (device globals) ----------------
__device__ __half g_h1 [NTOK * CDIM];
__device__ __half g_xz [NTOK * XZW];
__device__ __half g_u  [NTOK * DI];
__device__ __half g_xdh[NTOK * 64 + 512];   // padded for pipeline over-read
__device__ __half g_dt [NTOK * DI];
__device__ __half g_y  [NTOK * DI];
__device__ __half g_g  [NTOK * DI];
__device__ float  g_x1 [NTOK * CDIM];
__device__ __half g_h2 [NTOK * CDIM];
__device__ __half g_hid[NTOK * HIDD];
// chunked-scan summaries: [b][chunk][d]
__device__ float  g_ap [NBAT * NCHUNK * DI];
__device__ float  g_hl [NBAT * NCHUNK * DI];
__device__ float  g_h0 [NBAT * NCHUNK * DI];
// fp16 transposed weights ([N][K] K-major): w_in | w_out | fc1 | fc2 | xprojT | dtwT
#define WR_WIN  0
#define WR_WOUT (CDIM * XZW)
#define WR_FC1  (WR_WOUT + DI * CDIM)
#define WR_FC2  (WR_FC1 + CDIM * HIDD)
#define WR_XP   (WR_FC2 + HIDD * CDIM)
#define WR_DTW  (WR_XP + 64 * DI)
__device__ __half g_wr [WR_DTW + DI * 64 + 512];   // padded for over-read

// ---------------- helpers ----------------
__device__ __forceinline__ float siluf(float x) { return x / (1.f + expf(-x)); }
__device__ __forceinline__ float geluf(float x) {
    float x3 = x * x * x;
    return 0.5f * x * (1.f + tanhf(0.7978845608028654f * (x + 0.044715f * x3)));
}
__device__ __forceinline__ float softplusf(float x) {
    return (x > 20.f) ? x : log1pf(expf(x));
}
__device__ __forceinline__ uint32_t smem_u32(const void* p) {
    return (uint32_t)__cvta_generic_to_shared(p);
}
__device__ __forceinline__ void cp_async16(uint32_t dst, const void* src) {
    asm volatile("cp.async.ca.shared.global [%0], [%1], 16;" :: "r"(dst), "l"(src));
}
__device__ __forceinline__ void cp_commit() { asm volatile("cp.async.commit_group;"); }
template <int N>
__device__ __forceinline__ void cp_wait() {
    asm volatile("cp.async.wait_group %0;" :: "n"(N));
}
__device__ __forceinline__ void mma_f16(float* d, const uint32_t* a, const uint32_t* b) {
    asm volatile(
        "mma.sync.aligned.m16n8k16.row.col.f32.f16.f16.f32 "
        "{%0,%1,%2,%3}, {%4,%5,%6,%7}, {%8,%9}, {%0,%1,%2,%3};"
        : "+f"(d[0]), "+f"(d[1]), "+f"(d[2]), "+f"(d[3])
        : "r"(a[0]), "r"(a[1]), "r"(a[2]), "r"(a[3]), "r"(b[0]), "r"(b[1]));
}

// -------- weight transpose + fp16: dst[N][K] = half(src[K][N]) --------
__global__ void tpose_kernel(const float* __restrict__ src, __half* __restrict__ dst,
                             int K, int N)
{
    __shared__ float t[32][33];
    int kb = blockIdx.x << 5, nb = blockIdx.y << 5;
    int tx = threadIdx.x & 31, ty = threadIdx.x >> 5;
    #pragma unroll
    for (int i = 0; i < 32; i += 8)
        t[ty + i][tx] = src[(size_t)(kb + ty + i) * N + nb + tx];
    __syncthreads();
    #pragma unroll
    for (int i = 0; i < 32; i += 8)
        dst[(size_t)(nb + ty + i) * K + kb + tx] = __float2half(t[tx][ty + i]);
}

// xprojT[n][k] = n<26 ? x_proj_w[k][n] : 0     (64 x 768)
__global__ void xprojT_kernel(const float* __restrict__ W, __half* __restrict__ dst)
{
    int k = blockIdx.x * 256 + threadIdx.x;
    int n = blockIdx.y;
    dst[n * DI + k] = __float2half(n < 26 ? W[(size_t)k * 26 + n] : 0.f);
}

// dtwT[d][r] = r<24 ? dt_proj_w[r][d] : 0     (768 x 64)
__global__ void dtwT_kernel(const float* __restrict__ W, __half* __restrict__ dst)
{
    int i = blockIdx.x * 256 + threadIdx.x;
    int d = i >> 6, r = i & 63;
    dst[i] = __float2half(r < 24 ? W[(size_t)r * DI + d] : 0.f);
}

// ---------------- LayerNorm (warp per row) -> fp16 output ----------------
__global__ void ln_kernel(const float* __restrict__ x, const float* __restrict__ gam,
                          const float* __restrict__ bet, __half* __restrict__ out,
                          int ncols, float eps)
{
    int row  = blockIdx.x * (blockDim.x >> 5) + (threadIdx.x >> 5);
    int lane = threadIdx.x & 31;
    const float4* x4 = (const float4*)(x + (size_t)row * ncols);
    int cnt = (ncols >> 2) >> 5;
    float4 v[6];
    float s = 0.f, s2 = 0.f;
    for (int i = 0; i < cnt; i++) {
        v[i] = x4[lane + (i << 5)];
        s  += v[i].x + v[i].y + v[i].z + v[i].w;
        s2 += v[i].x * v[i].x + v[i].y * v[i].y + v[i].z * v[i].z + v[i].w * v[i].w;
    }
    #pragma unroll
    for (int o = 16; o; o >>= 1) {
        s  += __shfl_xor_sync(0xffffffffu, s,  o);
        s2 += __shfl_xor_sync(0xffffffffu, s2, o);
    }
    float inv_n = 1.f / (float)ncols;
    float mu = s * inv_n;
    float rstd = rsqrtf(fmaxf(s2 * inv_n - mu * mu, 0.f) + eps);
    const float4* g4 = (const float4*)gam;
    const float4* b4 = (const float4*)bet;
    __half2* o2 = (__half2*)(out + (size_t)row * ncols);
    for (int i = 0; i < cnt; i++) {
        float4 gg = g4[lane + (i << 5)], bb = b4[lane + (i << 5)];
        float rx = (v[i].x - mu) * rstd * gg.x + bb.x;
        float ry = (v[i].y - mu) * rstd * gg.y + bb.y;
        float rz = (v[i].z - mu) * rstd * gg.z + bb.z;
        float rw = (v[i].w - mu) * rstd * gg.w + bb.w;
        o2[2 * (lane + (i << 5))]     = __floats2half2_rn(rx, ry);
        o2[2 * (lane + (i << 5)) + 1] = __floats2half2_rn(rz, rw);
    }
}

// -------- depthwise 3x3 conv + silu (half in/out, f32 math) --------
__global__ void conv_silu_kernel(const __half* __restrict__ xz,
                                 const float* __restrict__ cw,
                                 __half* __restrict__ u)
{
    __shared__ float sx[3][32][128];
    int cc = blockIdx.x << 7;
    int h  = blockIdx.y;
    int b  = blockIdx.z;
    int tid = threadIdx.x;
    const __half* base = xz + (size_t)(b << 10) * XZW;

    for (int i = tid; i < 1536; i += 256) {
        int idx = i << 3;
        int r = idx >> 12;
        int rem = idx & 4095;
        int w = rem >> 7, c = rem & 127;
        int hh = h + r - 1;
        uint4 raw = make_uint4(0u, 0u, 0u, 0u);
        if ((unsigned)hh < 32u)
            raw = *(const uint4*)(base + (size_t)((hh << 5) + w) * XZW + cc + c);
        const __half2* hp = (const __half2*)&raw;
        float* dst = &sx[r][w][c];
        #pragma unroll
        for (int j = 0; j < 4; j++) {
            float2 f = __half22float2(hp[j]);
            dst[2 * j] = f.x; dst[2 * j + 1] = f.y;
        }
    }
    __syncthreads();

    int c  = tid & 127;
    int w0 = tid >> 7;
    float k[9];
    #pragma unroll
    for (int j = 0; j < 9; j++) k[j] = cw[(cc + c) * 9 + j];
    __half* urow = u + (size_t)((b << 10) + (h << 5)) * DI + cc + c;
    #pragma unroll
    for (int i = 0; i < 16; i++) {
        int w = w0 + (i << 1);
        float acc = 0.f;
        #pragma unroll
        for (int kh = 0; kh < 3; kh++)
            #pragma unroll
            for (int kw = 0; kw < 3; kw++) {
                int ww = w + kw - 1;
                if ((unsigned)ww < 32u)
                    acc = fmaf(sx[kh][ww][c], k[kh * 3 + kw], acc);
            }
        urow[(size_t)w * DI] = __float2half(siluf(acc));
    }
}

// ========== chunked selective scan (DS=1): A=summaries, B=combine, C=apply ==========
// pass A: per (b, chunk, d): aprod = prod(dA), hloc = local scan with h0=0
__global__ void scanA_kernel(const __half* __restrict__ u, const __half* __restrict__ dt,
                             const __half* __restrict__ xdh,
                             const float* __restrict__ A_log,
                             float* __restrict__ ap, float* __restrict__ hl)
{
    int gwarp = (blockIdx.x * blockDim.x + threadIdx.x) >> 5;
    int lane  = threadIdx.x & 31;
    int b   = gwarp / ((DI / 32) * NCHUNK);
    int rem = gwarp % ((DI / 32) * NCHUNK);
    int dg  = rem / NCHUNK, c = rem % NCHUNK;
    int d   = dg * 32 + lane;

    float Aval = -expf(A_log[d]);
    size_t tb = (size_t)b * LLEN + (size_t)c * CLEN;
    const __half* up = u   + tb * DI + d;
    const __half* dp = dt  + tb * DI + d;
    const __half* xp = xdh + tb * 64;

    float aprod = 1.f, h = 0.f;
    float uv = __half2float(up[0]), dtv = __half2float(dp[0]);
    float Bc = __low2float(*(const __half2*)(xp + 24));
    for (int l = 0; l < CLEN; l++) {
        float un = 0.f, dn = 0.f, Bn = 0.f;
        if (l + 1 < CLEN) {
            un = __half2float(up[(size_t)(l + 1) * DI]);
            dn = __half2float(dp[(size_t)(l + 1) * DI]);
            Bn = __low2float(*(const __half2*)(xp + (l + 1) * 64 + 24));
        }
        float dA = expf(dtv * Aval);
        h = fmaf(dA, h, dtv * Bc * uv);
        aprod *= dA;
        uv = un; dtv = dn; Bc = Bn;
    }
    int si = (b * NCHUNK + c) * DI + d;
    ap[si] = aprod; hl[si] = h;
}

// pass B: serial combine over chunks -> h0 per chunk
__global__ void scanB_kernel(const float* __restrict__ ap, const float* __restrict__ hl,
                             float* __restrict__ h0)
{
    int gwarp = (blockIdx.x * blockDim.x + threadIdx.x) >> 5;
    int lane  = threadIdx.x & 31;
    int b = gwarp / (DI / 32), dg = gwarp % (DI / 32);
    int d = dg * 32 + lane;
    float h = 0.f;
    #pragma unroll
    for (int c = 0; c < NCHUNK; c++) {
        int si = (b * NCHUNK + c) * DI + d;
        h0[si] = h;
        h = fmaf(ap[si], h, hl[si]);
    }
}

// pass C: recompute recurrence from exact h0, write y
__global__ void scanC_kernel(const __half* __restrict__ u, const __half* __restrict__ dt,
                             const __half* __restrict__ xdh,
                             const float* __restrict__ A_log, const float* __restrict__ Dp,
                             const float* __restrict__ h0, __half* __restrict__ y)
{
    int gwarp = (blockIdx.x * blockDim.x + threadIdx.x) >> 5;
    int lane  = threadIdx.x & 31;
    int b   = gwarp / ((DI / 32) * NCHUNK);
    int rem = gwarp % ((DI / 32) * NCHUNK);
    int dg  = rem / NCHUNK, c = rem % NCHUNK;
    int d   = dg * 32 + lane;

    float Aval = -expf(A_log[d]);
    float Dval = Dp[d];
    size_t tb = (size_t)b * LLEN + (size_t)c * CLEN;
    const __half* up = u   + tb * DI + d;
    const __half* dp = dt  + tb * DI + d;
    const __half* xp = xdh + tb * 64;
    __half*       yp = y   + tb * DI + d;

    float h = h0[(b * NCHUNK + c) * DI + d];
    float uv = __half2float(up[0]), dtv = __half2float(dp[0]);
    float2 bc = __half22float2(*(const __half2*)(xp + 24));
    float Bc = bc.x, Cc = bc.y;
    for (int l = 0; l < CLEN; l++) {
        float un = 0.f, dn = 0.f, Bn = 0.f, Cn = 0.f;
        if (l + 1 < CLEN) {
            un = __half2float(up[(size_t)(l + 1) * DI]);
            dn = __half2float(dp[(size_t)(l + 1) * DI]);
            float2 b2 = __half22float2(*(const __half2*)(xp + (l + 1) * 64 + 24));
            Bn = b2.x; Cn = b2.y;
        }
        float dA = expf(dtv * Aval);
        h = fmaf(dA, h, dtv * Bc * uv);
        yp[(size_t)l * DI] = __float2half(fmaf(h, Cc, uv * Dval));
        uv = un; dtv = dn; Bc = Bn; Cc = Cn;
    }
}

// ------------- out-norm over DI + gating (half in) -> fp16 out -------------
__global__ void lngate_kernel(const __half* __restrict__ y, const __half* __restrict__ xz,
                              const float* __restrict__ gam, const float* __restrict__ bet,
                              __half* __restrict__ out)
{
    int t    = blockIdx.x * (blockDim.x >> 5) + (threadIdx.x >> 5);
    int lane = threadIdx.x & 31;
    const __half2* y2 = (const __half2*)(y + (size_t)t * DI);
    float2 v[12];
    float s = 0.f, s2 = 0.f;
    #pragma unroll
    for (int i = 0; i < 12; i++) {
        v[i] = __half22float2(y2[lane + (i << 5)]);
        s  += v[i].x + v[i].y;
        s2 += v[i].x * v[i].x + v[i].y * v[i].y;
    }
    #pragma unroll
    for (int o = 16; o; o >>= 1) {
        s  += __shfl_xor_sync(0xffffffffu, s,  o);
        s2 += __shfl_xor_sync(0xffffffffu, s2, o);
    }
    float mu = s * (1.f / DI);
    float rstd = rsqrtf(fmaxf(s2 * (1.f / DI) - mu * mu, 0.f) + 1e-5f);
    const __half2* z2 = (const __half2*)(xz + (size_t)t * XZW + DI);
    const float2* g2 = (const float2*)gam;
    const float2* b2 = (const float2*)bet;
    __half2* o2 = (__half2*)(out + (size_t)t * DI);
    #pragma unroll
    for (int i = 0; i < 12; i++) {
        float2 zz = __half22float2(z2[lane + (i << 5)]);
        float2 gg = g2[lane + (i << 5)], bb = b2[lane + (i << 5)];
        float rx = ((v[i].x - mu) * rstd * gg.x + bb.x) * siluf(zz.x);
        float ry = ((v[i].y - mu) * rstd * gg.y + bb.y) * siluf(zz.y);
        o2[lane + (i << 5)] = __floats2half2_rn(rx, ry);
    }
}

// ===== fp16 TC GEMM (ldmatrix): C[M,N] = A[M,K] @ Bt[N,K]^T, f32 accum =====
// MODE: 0 plain, 1 bias+gelu, 2 bias+resid, 3 resid, 4 bias+softplus
#define GBM 128
#define GBK 32
#define STAGES 4
#define HSTR 40
constexpr int t5smem(int gbn) { return STAGES * (GBM + gbn) * HSTR * 2; }

template <int MODE, typename OutT, int GBN_, int WM, int WN>
__global__ void __launch_bounds__(256, 2)
gemm_f16(const __half* __restrict__ A, const __half* __restrict__ Bt,
         OutT* __restrict__ C, int M, int N, int K,
         const float* __restrict__ bias, const float* __restrict__ resid)
{
    constexpr int MI = GBM / (WM * 16);
    constexpr int NI = GBN_ / (WN * 8);
    constexpr int ASTG_ = GBM * HSTR;
    constexpr int BSTG_ = GBN_ * HSTR;
    constexpr int ACH = GBM / 64;
    constexpr int BCH = GBN_ / 64;

    extern __shared__ __half sh[];
    __half* As = sh;
    __half* Bs = sh + STAGES * ASTG_;

    int bm = blockIdx.y * GBM, bn = blockIdx.x * GBN_;
    int tid = threadIdx.x;
    int warp = tid >> 5, lane = tid & 31;
    int wm = warp / WN, wn = warp % WN;
    int g = lane >> 2, t = lane & 3;

    int arow[ACH], acol[ACH], brow[BCH], bcol[BCH];
    #pragma unroll
    for (int i = 0; i < ACH; i++) {
        int f = tid + i * 256;
        arow[i] = f >> 2; acol[i] = (f & 3) << 3;
    }
    #pragma unroll
    for (int i = 0; i < BCH; i++) {
        int f = tid + i * 256;
        brow[i] = f >> 2; bcol[i] = (f & 3) << 3;
    }

    auto load_stage = [&](int s, int k0) {
        __half* Ad = As + s * ASTG_;
        __half* Bd = Bs + s * BSTG_;
        #pragma unroll
        for (int i = 0; i < ACH; i++)
            cp_async16(smem_u32(&Ad[arow[i] * HSTR + acol[i]]),
                       A + (size_t)(bm + arow[i]) * K + k0 + acol[i]);
        #pragma unroll
        for (int i = 0; i < BCH; i++)
            cp_async16(smem_u32(&Bd[brow[i] * HSTR + bcol[i]]),
                       Bt + (size_t)(bn + brow[i]) * K + k0 + bcol[i]);
        cp_commit();
    };

    int nIter = K / GBK;
    #pragma unroll
    for (int s = 0; s < STAGES - 1; s++) load_stage(s, s * GBK);

    float acc[MI][NI][4];
    #pragma unroll
    for (int i = 0; i < MI; i++)
        #pragma unroll
        for (int j = 0; j < NI; j++)
            #pragma unroll
            for (int r = 0; r < 4; r++) acc[i][j][r] = 0.f;

    int asel = lane >> 3;
    int a_r  = (asel & 1) * 8 + (lane & 7);
    int a_c  = (asel >> 1) * 8;
    int b_r  = lane & 7;
    int b_c  = ((lane >> 3) & 1) * 8;

    for (int it = 0; it < nIter; it++) {
        cp_wait<STAGES - 2>();
        __syncthreads();
        int pf = it + STAGES - 1;
        if (pf < nIter) load_stage(pf % STAGES, pf * GBK);
        else            cp_commit();

        const __half* Ab = As + (it % STAGES) * ASTG_;
        const __half* Bb = Bs + (it % STAGES) * BSTG_;
        #pragma unroll
        for (int ks = 0; ks < 2; ks++) {
            int kb = ks * 16;
            uint32_t af[MI][4], bf[NI][2];
            #pragma unroll
            for (int mi = 0; mi < MI; mi++) {
                uint32_t ad = smem_u32(&Ab[(wm * (MI * 16) + mi * 16 + a_r) * HSTR + kb + a_c]);
                asm volatile(
                    "ldmatrix.sync.aligned.m8n8.x4.shared.b16 {%0,%1,%2,%3}, [%4];"
                    : "=r"(af[mi][0]), "=r"(af[mi][1]), "=r"(af[mi][2]), "=r"(af[mi][3])
                    : "r"(ad));
            }
            #pragma unroll
            for (int ni = 0; ni < NI; ni++) {
                uint32_t bd = smem_u32(&Bb[(wn * (NI * 8) + ni * 8 + b_r) * HSTR + kb + b_c]);
                asm volatile(
                    "ldmatrix.sync.aligned.m8n8.x2.shared.b16 {%0,%1}, [%2];"
                    : "=r"(bf[ni][0]), "=r"(bf[ni][1])
                    : "r"(bd));
            }
            #pragma unroll
            for (int mi = 0; mi < MI; mi++)
                #pragma unroll
                for (int ni = 0; ni < NI; ni++)
                    mma_f16(acc[mi][ni], af[mi], bf[ni]);
        }
    }

    #pragma unroll
    for (int mi = 0; mi < MI; mi++) {
        #pragma unroll
        for (int half_ = 0; half_ < 2; half_++) {
            int row = bm + wm * (MI * 16) + mi * 16 + g + half_ * 8;
            #pragma unroll
            for (int ni = 0; ni < NI; ni++) {
                int col = bn + wn * (NI * 8) + ni * 8 + 2 * t;
                float v0 = acc[mi][ni][half_ * 2 + 0];
                float v1 = acc[mi][ni][half_ * 2 + 1];
                if (MODE == 1) {
                    float2 bb = *(const float2*)(bias + col);
                    v0 = geluf(v0 + bb.x); v1 = geluf(v1 + bb.y);
                } else if (MODE == 2) {
                    float2 bb = *(const float2*)(bias + col);
                    float2 rs = *(const float2*)(resid + (size_t)row * N + col);
                    v0 += bb.x + rs.x; v1 += bb.y + rs.y;
                } else if (MODE == 3) {
                    float2 rs = *(const float2*)(resid + (size_t)row * N + col);
                    v0 += rs.x; v1 += rs.y;
                } else if (MODE == 4) {
                    float2 bb = *(const float2*)(bias + col);
                    v0 = softplusf(v0 + bb.x); v1 = softplusf(v1 + bb.y);
                }
                if (sizeof(OutT) == 2) {
                    *(__half2*)((__half*)C + (size_t)row * N + col) =
                        __floats2half2_rn(v0, v1);
                } else {
                    *(float2*)((float*)C + (size_t)row * N + col) = make_float2(v0, v1);
                }
            }
        }
    }
}

// ---------------- launch ----------------
extern "C" void kernel_launch(void* const* d_in, const int* in_sizes, int n_in,
                              void* d_out, int out_size)
{
    const float* x        = (const float*)d_in[0];
    const float* ln1_g    = (const float*)d_in[1];
    const float* ln1_b    = (const float*)d_in[2];
    const float* w_in     = (const float*)d_in[3];
    const float* conv_w   = (const float*)d_in[4];
    const float* x_proj_w = (const float*)d_in[5];
    const float* dt_w     = (const float*)d_in[6];
    const float* dt_b     = (const float*)d_in[7];
    const float* A_log    = (const float*)d_in[8];
    const float* Dp       = (const float*)d_in[9];
    const float* on_g     = (const float*)d_in[10];
    const float* on_b     = (const float*)d_in[11];
    const float* w_out    = (const float*)d_in[12];
    const float* ln2_g    = (const float*)d_in[13];
    const float* ln2_b    = (const float*)d_in[14];
    const float* fc1_w    = (const float*)d_in[15];
    const float* fc1_b    = (const float*)d_in[16];
    const float* fc2_w    = (const float*)d_in[17];
    const float* fc2_b    = (const float*)d_in[18];
    float* out = (float*)d_out;

    __half *h1, *xz, *u, *xdh, *dt, *y, *g, *h2, *hid, *wr;
    float *x1, *ap, *hl, *h0;
    cudaGetSymbolAddress((void**)&h1,  g_h1);
    cudaGetSymbolAddress((void**)&xz,  g_xz);
    cudaGetSymbolAddress((void**)&u,   g_u);
    cudaGetSymbolAddress((void**)&xdh, g_xdh);
    cudaGetSymbolAddress((void**)&dt,  g_dt);
    cudaGetSymbolAddress((void**)&y,   g_y);
    cudaGetSymbolAddress((void**)&g,   g_g);
    cudaGetSymbolAddress((void**)&x1,  g_x1);
    cudaGetSymbolAddress((void**)&h2,  g_h2);
    cudaGetSymbolAddress((void**)&hid, g_hid);
    cudaGetSymbolAddress((void**)&wr,  g_wr);
    cudaGetSymbolAddress((void**)&ap,  g_ap);
    cudaGetSymbolAddress((void**)&hl,  g_hl);
    cudaGetSymbolAddress((void**)&h0,  g_h0);

    cudaFuncSetAttribute((void*)gemm_f16<0, __half, 128, 2, 4>, cudaFuncAttributeMaxDynamicSharedMemorySize, t5smem(128));
    cudaFuncSetAttribute((void*)gemm_f16<1, __half, 128, 2, 4>, cudaFuncAttributeMaxDynamicSharedMemorySize, t5smem(128));
    cudaFuncSetAttribute((void*)gemm_f16<4, __half, 128, 2, 4>, cudaFuncAttributeMaxDynamicSharedMemorySize, t5smem(128));
    cudaFuncSetAttribute((void*)gemm_f16<0, __half, 64, 4, 2>,  cudaFuncAttributeMaxDynamicSharedMemorySize, t5smem(64));
    cudaFuncSetAttribute((void*)gemm_f16<2, float, 64, 4, 2>,   cudaFuncAttributeMaxDynamicSharedMemorySize, t5smem(64));
    cudaFuncSetAttribute((void*)gemm_f16<3, float, 64, 4, 2>,   cudaFuncAttributeMaxDynamicSharedMemorySize, t5smem(64));

    // 0. weight prep
    tpose_kernel<<<dim3(CDIM / 32, XZW / 32), 256>>>(w_in,  wr + WR_WIN,  CDIM, XZW);
    tpose_kernel<<<dim3(DI / 32, CDIM / 32), 256>>>(w_out, wr + WR_WOUT, DI, CDIM);
    tpose_kernel<<<dim3(CDIM / 32, HIDD / 32), 256>>>(fc1_w, wr + WR_FC1, CDIM, HIDD);
    tpose_kernel<<<dim3(HIDD / 32, CDIM / 32), 256>>>(fc2_w, wr + WR_FC2, HIDD, CDIM);
    xprojT_kernel<<<dim3(3, 64), 256>>>(x_proj_w, wr + WR_XP);
    dtwT_kernel<<<192, 256>>>(dt_w, wr + WR_DTW);

    // 1. h1 = LN(x) -> fp16
    ln_kernel<<<NTOK / 8, 256>>>(x, ln1_g, ln1_b, h1, CDIM, 1e-6f);
    // 2. xz = h1 @ w_in
    gemm_f16<0, __half, 128, 2, 4><<<dim3(XZW / 128, NTOK / GBM), 256, t5smem(128)>>>(
        h1, wr + WR_WIN, xz, NTOK, XZW, CDIM, nullptr, nullptr);
    // 3. u = silu(dwconv3x3(xm))
    conv_silu_kernel<<<dim3(DI / 128, 32, NBAT), 256>>>(xz, conv_w, u);
    // 4. xd = u @ xprojT^T
    gemm_f16<0, __half, 64, 4, 2><<<dim3(1, NTOK / GBM), 256, t5smem(64)>>>(
        u, wr + WR_XP, xdh, NTOK, 64, DI, nullptr, nullptr);
    // 5. dt = softplus(xd @ dtwT^T + dtb)
    gemm_f16<4, __half, 128, 2, 4><<<dim3(DI / 128, NTOK / GBM), 256, t5smem(128)>>>(
        xdh, wr + WR_DTW, dt, NTOK, DI, 64, dt_b, nullptr);
    // 6. chunked scan: A (summaries), B (combine), C (apply + y)
    scanA_kernel<<<NBAT * (DI / 32) * NCHUNK / 8, 256>>>(u, dt, xdh, A_log, ap, hl);
    scanB_kernel<<<NBAT * (DI / 32) / 8, 256>>>(ap, hl, h0);
    scanC_kernel<<<NBAT * (DI / 32) * NCHUNK / 8, 256>>>(u, dt, xdh, A_log, Dp, h0, y);
    // 7. g = LN_out(y) * silu(z) -> fp16
    lngate_kernel<<<NTOK / 8, 256>>>(y, xz, on_g, on_b, g);
    // 8. x1 = g @ w_out + x
    gemm_f16<3, float, 64, 4, 2><<<dim3(CDIM / 64, NTOK / GBM), 256, t5smem(64)>>>(
        g, wr + WR_WOUT, x1, NTOK, CDIM, DI, nullptr, x);
    // 9. h2 = LN(x1) -> fp16
    ln_kernel<<<NTOK / 8, 256>>>(x1, ln2_g, ln2_b, h2, CDIM, 1e-6f);
    // 10. hid = gelu(h2 @ fc1_w + fc1_b) -> fp16
    gemm_f16<1, __half, 128, 2, 4><<<dim3(HIDD / 128, NTOK / GBM), 256, t5smem(128)>>>(
        h2, wr + WR_FC1, hid, NTOK, HIDD, CDIM, fc1_b, nullptr);
    // 11. out = hid @ fc2_w + fc2_b + x1
    gemm_f16<2, float, 64, 4, 2><<<dim3(CDIM / 64, NTOK / GBM), 256, t5smem(64)>>>(
        hid, wr + WR_FC2, out, NTOK, CDIM, HIDD, fc2_b, x1);
}

// round 16
// speedup vs baseline: 4.7209x; 1.0317x over previous
#include <cuda_runtime.h>
#include <cuda_fp16.h>
#include <math.h>
#include <stdint.h>

#define NTOK 16384
#define CDIM 384
#define DI   768
#define LLEN 1024
#define NBAT 16
#define HIDD 1536
#define XZW  1536   // 2*DI
#define NCHUNK 16
#define CLEN   64    // LLEN / NCHUNK

// ---------------- scratch (device globals) ----------------
__device__ __half g_h1 [NTOK * CDIM];
__device__ __half g_xz [NTOK * XZW];
__device__ __half g_u  [NTOK * DI];
__device__ __half g_xdh[NTOK * 64 + 512];
__device__ __half g_dt [NTOK * DI];
__device__ __half g_g  [NTOK * DI];
__device__ float  g_x1 [NTOK * CDIM];
__device__ __half g_h2 [NTOK * CDIM];
__device__ __half g_hid[NTOK * HIDD];
// chunked-scan summaries: [b][chunk][d]
__device__ float  g_ap [NBAT * NCHUNK * DI];
__device__ float  g_hl [NBAT * NCHUNK * DI];
__device__ float  g_h0 [NBAT * NCHUNK * DI];
// fp16 transposed weights ([N][K] K-major): w_in | w_out | fc1 | fc2 | xprojT | dtwT
#define WR_WIN  0
#define WR_WOUT (CDIM * XZW)
#define WR_FC1  (WR_WOUT + DI * CDIM)
#define WR_FC2  (WR_FC1 + CDIM * HIDD)
#define WR_XP   (WR_FC2 + HIDD * CDIM)
#define WR_DTW  (WR_XP + 64 * DI)
__device__ __half g_wr [WR_DTW + DI * 64 + 512];

// ---------------- helpers ----------------
__device__ __forceinline__ float siluf(float x) { return x / (1.f + expf(-x)); }
__device__ __forceinline__ float geluf(float x) {
    float x3 = x * x * x;
    return 0.5f * x * (1.f + tanhf(0.7978845608028654f * (x + 0.044715f * x3)));
}
__device__ __forceinline__ float softplusf(float x) {
    return (x > 20.f) ? x : log1pf(expf(x));
}
__device__ __forceinline__ uint32_t smem_u32(const void* p) {
    return (uint32_t)__cvta_generic_to_shared(p);
}
__device__ __forceinline__ void cp_async16(uint32_t dst, const void* src) {
    asm volatile("cp.async.ca.shared.global [%0], [%1], 16;" :: "r"(dst), "l"(src));
}
__device__ __forceinline__ void cp_commit() { asm volatile("cp.async.commit_group;"); }
template <int N>
__device__ __forceinline__ void cp_wait() {
    asm volatile("cp.async.wait_group %0;" :: "n"(N));
}
__device__ __forceinline__ void mma_f16(float* d, const uint32_t* a, const uint32_t* b) {
    asm volatile(
        "mma.sync.aligned.m16n8k16.row.col.f32.f16.f16.f32 "
        "{%0,%1,%2,%3}, {%4,%5,%6,%7}, {%8,%9}, {%0,%1,%2,%3};"
        : "+f"(d[0]), "+f"(d[1]), "+f"(d[2]), "+f"(d[3])
        : "r"(a[0]), "r"(a[1]), "r"(a[2]), "r"(a[3]), "r"(b[0]), "r"(b[1]));
}

// ===== unified weight prep: 6 transposes (+pad) in ONE kernel =====
// dst[n*Kpad + k] = (k<K && n<srcN) ? half(src[k*srcN + n]) : 0
__global__ void prep_kernel(const float* __restrict__ w_in, const float* __restrict__ w_out,
                            const float* __restrict__ fc1, const float* __restrict__ fc2,
                            const float* __restrict__ xproj, const float* __restrict__ dtw,
                            __half* __restrict__ wr)
{
    __shared__ float t[32][33];
    int bid = blockIdx.x;
    const float* src; __half* dst;
    int K, Kpad, srcN, tileN, rel;
    if (bid < 576)       { src = w_in;  dst = wr + WR_WIN;  K = 384;  Kpad = 384;  srcN = 1536; tileN = 48; rel = bid; }
    else if (bid < 864)  { src = w_out; dst = wr + WR_WOUT; K = 768;  Kpad = 768;  srcN = 384;  tileN = 12; rel = bid - 576; }
    else if (bid < 1440) { src = fc1;   dst = wr + WR_FC1;  K = 384;  Kpad = 384;  srcN = 1536; tileN = 48; rel = bid - 864; }
    else if (bid < 2016) { src = fc2;   dst = wr + WR_FC2;  K = 1536; Kpad = 1536; srcN = 384;  tileN = 12; rel = bid - 1440; }
    else if (bid < 2064) { src = xproj; dst = wr + WR_XP;   K = 768;  Kpad = 768;  srcN = 26;   tileN = 2;  rel = bid - 2016; }
    else                 { src = dtw;   dst = wr + WR_DTW;  K = 24;   Kpad = 64;   srcN = 768;  tileN = 24; rel = bid - 2064; }
    int kb = (rel / tileN) << 5, nb = (rel % tileN) << 5;
    int tx = threadIdx.x & 31, ty = threadIdx.x >> 5;
    #pragma unroll
    for (int i = 0; i < 32; i += 8) {
        int k = kb + ty + i, n = nb + tx;
        t[ty + i][tx] = (k < K && n < srcN) ? src[(size_t)k * srcN + n] : 0.f;
    }
    __syncthreads();
    #pragma unroll
    for (int i = 0; i < 32; i += 8)
        dst[(size_t)(nb + ty + i) * Kpad + kb + tx] = __float2half(t[tx][ty + i]);
}

// ---------------- LayerNorm (warp per row) -> fp16 output ----------------
__global__ void ln_kernel(const float* __restrict__ x, const float* __restrict__ gam,
                          const float* __restrict__ bet, __half* __restrict__ out,
                          int ncols, float eps)
{
    int row  = blockIdx.x * (blockDim.x >> 5) + (threadIdx.x >> 5);
    int lane = threadIdx.x & 31;
    const float4* x4 = (const float4*)(x + (size_t)row * ncols);
    int cnt = (ncols >> 2) >> 5;
    float4 v[6];
    float s = 0.f, s2 = 0.f;
    for (int i = 0; i < cnt; i++) {
        v[i] = x4[lane + (i << 5)];
        s  += v[i].x + v[i].y + v[i].z + v[i].w;
        s2 += v[i].x * v[i].x + v[i].y * v[i].y + v[i].z * v[i].z + v[i].w * v[i].w;
    }
    #pragma unroll
    for (int o = 16; o; o >>= 1) {
        s  += __shfl_xor_sync(0xffffffffu, s,  o);
        s2 += __shfl_xor_sync(0xffffffffu, s2, o);
    }
    float inv_n = 1.f / (float)ncols;
    float mu = s * inv_n;
    float rstd = rsqrtf(fmaxf(s2 * inv_n - mu * mu, 0.f) + eps);
    const float4* g4 = (const float4*)gam;
    const float4* b4 = (const float4*)bet;
    __half2* o2 = (__half2*)(out + (size_t)row * ncols);
    for (int i = 0; i < cnt; i++) {
        float4 gg = g4[lane + (i << 5)], bb = b4[lane + (i << 5)];
        float rx = (v[i].x - mu) * rstd * gg.x + bb.x;
        float ry = (v[i].y - mu) * rstd * gg.y + bb.y;
        float rz = (v[i].z - mu) * rstd * gg.z + bb.z;
        float rw = (v[i].w - mu) * rstd * gg.w + bb.w;
        o2[2 * (lane + (i << 5))]     = __floats2half2_rn(rx, ry);
        o2[2 * (lane + (i << 5)) + 1] = __floats2half2_rn(rz, rw);
    }
}

// -------- depthwise 3x3 conv + silu (half in/out, f32 math) --------
__global__ void conv_silu_kernel(const __half* __restrict__ xz,
                                 const float* __restrict__ cw,
                                 __half* __restrict__ u)
{
    __shared__ float sx[3][32][128];
    int cc = blockIdx.x << 7;
    int h  = blockIdx.y;
    int b  = blockIdx.z;
    int tid = threadIdx.x;
    const __half* base = xz + (size_t)(b << 10) * XZW;

    for (int i = tid; i < 1536; i += 256) {
        int idx = i << 3;
        int r = idx >> 12;
        int rem = idx & 4095;
        int w = rem >> 7, c = rem & 127;
        int hh = h + r - 1;
        uint4 raw = make_uint4(0u, 0u, 0u, 0u);
        if ((unsigned)hh < 32u)
            raw = *(const uint4*)(base + (size_t)((hh << 5) + w) * XZW + cc + c);
        const __half2* hp = (const __half2*)&raw;
        float* dst = &sx[r][w][c];
        #pragma unroll
        for (int j = 0; j < 4; j++) {
            float2 f = __half22float2(hp[j]);
            dst[2 * j] = f.x; dst[2 * j + 1] = f.y;
        }
    }
    __syncthreads();

    int c  = tid & 127;
    int w0 = tid >> 7;
    float k[9];
    #pragma unroll
    for (int j = 0; j < 9; j++) k[j] = cw[(cc + c) * 9 + j];
    __half* urow = u + (size_t)((b << 10) + (h << 5)) * DI + cc + c;
    #pragma unroll
    for (int i = 0; i < 16; i++) {
        int w = w0 + (i << 1);
        float acc = 0.f;
        #pragma unroll
        for (int kh = 0; kh < 3; kh++)
            #pragma unroll
            for (int kw = 0; kw < 3; kw++) {
                int ww = w + kw - 1;
                if ((unsigned)ww < 32u)
                    acc = fmaf(sx[kh][ww][c], k[kh * 3 + kw], acc);
            }
        urow[(size_t)w * DI] = __float2half(siluf(acc));
    }
}

// ========== chunked selective scan (DS=1) ==========
// pass A: per (b, chunk, d): aprod = prod(dA), hloc = local scan with h0=0
__global__ void scanA_kernel(const __half* __restrict__ u, const __half* __restrict__ dt,
                             const __half* __restrict__ xdh,
                             const float* __restrict__ A_log,
                             float* __restrict__ ap, float* __restrict__ hl)
{
    int gwarp = (blockIdx.x * blockDim.x + threadIdx.x) >> 5;
    int lane  = threadIdx.x & 31;
    int b   = gwarp / ((DI / 32) * NCHUNK);
    int rem = gwarp % ((DI / 32) * NCHUNK);
    int dg  = rem / NCHUNK, c = rem % NCHUNK;
    int d   = dg * 32 + lane;

    float Aval = -expf(A_log[d]);
    size_t tb = (size_t)b * LLEN + (size_t)c * CLEN;
    const __half* up = u   + tb * DI + d;
    const __half* dp = dt  + tb * DI + d;
    const __half* xp = xdh + tb * 64;

    float aprod = 1.f, h = 0.f;
    float uv = __half2float(up[0]), dtv = __half2float(dp[0]);
    float Bc = __low2float(*(const __half2*)(xp + 24));
    for (int l = 0; l < CLEN; l++) {
        float un = 0.f, dn = 0.f, Bn = 0.f;
        if (l + 1 < CLEN) {
            un = __half2float(up[(size_t)(l + 1) * DI]);
            dn = __half2float(dp[(size_t)(l + 1) * DI]);
            Bn = __low2float(*(const __half2*)(xp + (l + 1) * 64 + 24));
        }
        float dA = expf(dtv * Aval);
        h = fmaf(dA, h, dtv * Bc * uv);
        aprod *= dA;
        uv = un; dtv = dn; Bc = Bn;
    }
    int si = (b * NCHUNK + c) * DI + d;
    ap[si] = aprod; hl[si] = h;
}

// pass B: serial combine over chunks -> h0 per chunk
__global__ void scanB_kernel(const float* __restrict__ ap, const float* __restrict__ hl,
                             float* __restrict__ h0)
{
    int gwarp = (blockIdx.x * blockDim.x + threadIdx.x) >> 5;
    int lane  = threadIdx.x & 31;
    int b = gwarp / (DI / 32), dg = gwarp % (DI / 32);
    int d = dg * 32 + lane;
    float h = 0.f;
    #pragma unroll
    for (int c = 0; c < NCHUNK; c++) {
        int si = (b * NCHUNK + c) * DI + d;
        h0[si] = h;
        h = fmaf(ap[si], h, hl[si]);
    }
}

// pass C (FUSED with out-norm + gate): recompute from exact h0, y -> smem,
// then LN over DI + silu(z) gating straight from smem to g. One block per (b,chunk).
#define SCANC_SMEM (CLEN * DI * 2)   // 98304 bytes
__global__ void __launch_bounds__(768)
scanC_kernel(const __half* __restrict__ u, const __half* __restrict__ dt,
             const __half* __restrict__ xdh,
             const float* __restrict__ A_log, const float* __restrict__ Dp,
             const float* __restrict__ h0, const __half* __restrict__ xz,
             const float* __restrict__ gam, const float* __restrict__ bet,
             __half* __restrict__ gout)
{
    extern __shared__ __half ys[];   // [CLEN][DI]
    int blk = blockIdx.x;            // b*NCHUNK + c
    int b = blk / NCHUNK, c = blk % NCHUNK;
    int d = threadIdx.x;             // 0..767

    float Aval = -expf(A_log[d]);
    float Dval = Dp[d];
    size_t tb = (size_t)b * LLEN + (size_t)c * CLEN;
    const __half* up = u   + tb * DI + d;
    const __half* dp = dt  + tb * DI + d;
    const __half* xp = xdh + tb * 64;

    float h = h0[blk * DI + d];
    float uv = __half2float(up[0]), dtv = __half2float(dp[0]);
    float2 bc = __half22float2(*(const __half2*)(xp + 24));
    float Bc = bc.x, Cc = bc.y;
    for (int l = 0; l < CLEN; l++) {
        float un = 0.f, dn = 0.f, Bn = 0.f, Cn = 0.f;
        if (l + 1 < CLEN) {
            un = __half2float(up[(size_t)(l + 1) * DI]);
            dn = __half2float(dp[(size_t)(l + 1) * DI]);
            float2 b2 = __half22float2(*(const __half2*)(xp + (l + 1) * 64 + 24));
            Bn = b2.x; Cn = b2.y;
        }
        float dA = expf(dtv * Aval);
        h = fmaf(dA, h, dtv * Bc * uv);
        ys[l * DI + d] = __float2half(fmaf(h, Cc, uv * Dval));
        uv = un; dtv = dn; Bc = Bn; Cc = Cn;
    }
    __syncthreads();

    // LN + gate phase: warp per token, tokens strided by 24 warps
    int warp = threadIdx.x >> 5, lane = threadIdx.x & 31;
    for (int l = warp; l < CLEN; l += 24) {
        const __half2* y2 = (const __half2*)(ys + l * DI);
        float2 v[12];
        float s = 0.f, s2 = 0.f;
        #pragma unroll
        for (int i = 0; i < 12; i++) {
            v[i] = __half22float2(y2[lane + (i << 5)]);
            s  += v[i].x + v[i].y;
            s2 += v[i].x * v[i].x + v[i].y * v[i].y;
        }
        #pragma unroll
        for (int o = 16; o; o >>= 1) {
            s  += __shfl_xor_sync(0xffffffffu, s,  o);
            s2 += __shfl_xor_sync(0xffffffffu, s2, o);
        }
        float mu = s * (1.f / DI);
        float rstd = rsqrtf(fmaxf(s2 * (1.f / DI) - mu * mu, 0.f) + 1e-5f);
        size_t tok = tb + l;
        const __half2* z2 = (const __half2*)(xz + tok * XZW + DI);
        const float2* g2 = (const float2*)gam;
        const float2* b2 = (const float2*)bet;
        __half2* o2 = (__half2*)(gout + tok * DI);
        #pragma unroll
        for (int i = 0; i < 12; i++) {
            float2 zz = __half22float2(z2[lane + (i << 5)]);
            float2 gg = g2[lane + (i << 5)], bb = b2[lane + (i << 5)];
            float rx = ((v[i].x - mu) * rstd * gg.x + bb.x) * siluf(zz.x);
            float ry = ((v[i].y - mu) * rstd * gg.y + bb.y) * siluf(zz.y);
            o2[lane + (i << 5)] = __floats2half2_rn(rx, ry);
        }
    }
}

// ===== fp16 TC GEMM (ldmatrix): C[M,N] = A[M,K] @ Bt[N,K]^T, f32 accum =====
// MODE: 0 plain, 1 bias+gelu, 2 bias+resid, 3 resid, 4 bias+softplus
#define GBM 128
#define GBK 32
#define STAGES 4
#define HSTR 40
constexpr int t5smem(int gbn) { return STAGES * (GBM + gbn) * HSTR * 2; }

template <int MODE, typename OutT, int GBN_, int WM, int WN>
__global__ void __launch_bounds__(256, 2)
gemm_f16(const __half* __restrict__ A, const __half* __restrict__ Bt,
         OutT* __restrict__ C, int M, int N, int K,
         const float* __restrict__ bias, const float* __restrict__ resid)
{
    constexpr int MI = GBM / (WM * 16);
    constexpr int NI = GBN_ / (WN * 8);
    constexpr int ASTG_ = GBM * HSTR;
    constexpr int BSTG_ = GBN_ * HSTR;
    constexpr int ACH = GBM / 64;
    constexpr int BCH = GBN_ / 64;

    extern __shared__ __half sh[];
    __half* As = sh;
    __half* Bs = sh + STAGES * ASTG_;

    int bm = blockIdx.y * GBM, bn = blockIdx.x * GBN_;
    int tid = threadIdx.x;
    int warp = tid >> 5, lane = tid & 31;
    int wm = warp / WN, wn = warp % WN;
    int g = lane >> 2, t = lane & 3;

    int arow[ACH], acol[ACH], brow[BCH], bcol[BCH];
    #pragma unroll
    for (int i = 0; i < ACH; i++) {
        int f = tid + i * 256;
        arow[i] = f >> 2; acol[i] = (f & 3) << 3;
    }
    #pragma unroll
    for (int i = 0; i < BCH; i++) {
        int f = tid + i * 256;
        brow[i] = f >> 2; bcol[i] = (f & 3) << 3;
    }

    auto load_stage = [&](int s, int k0) {
        __half* Ad = As + s * ASTG_;
        __half* Bd = Bs + s * BSTG_;
        #pragma unroll
        for (int i = 0; i < ACH; i++)
            cp_async16(smem_u32(&Ad[arow[i] * HSTR + acol[i]]),
                       A + (size_t)(bm + arow[i]) * K + k0 + acol[i]);
        #pragma unroll
        for (int i = 0; i < BCH; i++)
            cp_async16(smem_u32(&Bd[brow[i] * HSTR + bcol[i]]),
                       Bt + (size_t)(bn + brow[i]) * K + k0 + bcol[i]);
        cp_commit();
    };

    int nIter = K / GBK;
    #pragma unroll
    for (int s = 0; s < STAGES - 1; s++) load_stage(s, s * GBK);

    float acc[MI][NI][4];
    #pragma unroll
    for (int i = 0; i < MI; i++)
        #pragma unroll
        for (int j = 0; j < NI; j++)
            #pragma unroll
            for (int r = 0; r < 4; r++) acc[i][j][r] = 0.f;

    int asel = lane >> 3;
    int a_r  = (asel & 1) * 8 + (lane & 7);
    int a_c  = (asel >> 1) * 8;
    int b_r  = lane & 7;
    int b_c  = ((lane >> 3) & 1) * 8;

    for (int it = 0; it < nIter; it++) {
        cp_wait<STAGES - 2>();
        __syncthreads();
        int pf = it + STAGES - 1;
        if (pf < nIter) load_stage(pf % STAGES, pf * GBK);
        else            cp_commit();

        const __half* Ab = As + (it % STAGES) * ASTG_;
        const __half* Bb = Bs + (it % STAGES) * BSTG_;
        #pragma unroll
        for (int ks = 0; ks < 2; ks++) {
            int kb = ks * 16;
            uint32_t af[MI][4], bf[NI][2];
            #pragma unroll
            for (int mi = 0; mi < MI; mi++) {
                uint32_t ad = smem_u32(&Ab[(wm * (MI * 16) + mi * 16 + a_r) * HSTR + kb + a_c]);
                asm volatile(
                    "ldmatrix.sync.aligned.m8n8.x4.shared.b16 {%0,%1,%2,%3}, [%4];"
                    : "=r"(af[mi][0]), "=r"(af[mi][1]), "=r"(af[mi][2]), "=r"(af[mi][3])
                    : "r"(ad));
            }
            #pragma unroll
            for (int ni = 0; ni < NI; ni++) {
                uint32_t bd = smem_u32(&Bb[(wn * (NI * 8) + ni * 8 + b_r) * HSTR + kb + b_c]);
                asm volatile(
                    "ldmatrix.sync.aligned.m8n8.x2.shared.b16 {%0,%1}, [%2];"
                    : "=r"(bf[ni][0]), "=r"(bf[ni][1])
                    : "r"(bd));
            }
            #pragma unroll
            for (int mi = 0; mi < MI; mi++)
                #pragma unroll
                for (int ni = 0; ni < NI; ni++)
                    mma_f16(acc[mi][ni], af[mi], bf[ni]);
        }
    }

    #pragma unroll
    for (int mi = 0; mi < MI; mi++) {
        #pragma unroll
        for (int half_ = 0; half_ < 2; half_++) {
            int row = bm + wm * (MI * 16) + mi * 16 + g + half_ * 8;
            #pragma unroll
            for (int ni = 0; ni < NI; ni++) {
                int col = bn + wn * (NI * 8) + ni * 8 + 2 * t;
                float v0 = acc[mi][ni][half_ * 2 + 0];
                float v1 = acc[mi][ni][half_ * 2 + 1];
                if (MODE == 1) {
                    float2 bb = *(const float2*)(bias + col);
                    v0 = geluf(v0 + bb.x); v1 = geluf(v1 + bb.y);
                } else if (MODE == 2) {
                    float2 bb = *(const float2*)(bias + col);
                    float2 rs = *(const float2*)(resid + (size_t)row * N + col);
                    v0 += bb.x + rs.x; v1 += bb.y + rs.y;
                } else if (MODE == 3) {
                    float2 rs = *(const float2*)(resid + (size_t)row * N + col);
                    v0 += rs.x; v1 += rs.y;
                } else if (MODE == 4) {
                    float2 bb = *(const float2*)(bias + col);
                    v0 = softplusf(v0 + bb.x); v1 = softplusf(v1 + bb.y);
                }
                if (sizeof(OutT) == 2) {
                    *(__half2*)((__half*)C + (size_t)row * N + col) =
                        __floats2half2_rn(v0, v1);
                } else {
                    *(float2*)((float*)C + (size_t)row * N + col) = make_float2(v0, v1);
                }
            }
        }
    }
}

// ---------------- launch ----------------
extern "C" void kernel_launch(void* const* d_in, const int* in_sizes, int n_in,
                              void* d_out, int out_size)
{
    const float* x        = (const float*)d_in[0];
    const float* ln1_g    = (const float*)d_in[1];
    const float* ln1_b    = (const float*)d_in[2];
    const float* w_in     = (const float*)d_in[3];
    const float* conv_w   = (const float*)d_in[4];
    const float* x_proj_w = (const float*)d_in[5];
    const float* dt_w     = (const float*)d_in[6];
    const float* dt_b     = (const float*)d_in[7];
    const float* A_log    = (const float*)d_in[8];
    const float* Dp       = (const float*)d_in[9];
    const float* on_g     = (const float*)d_in[10];
    const float* on_b     = (const float*)d_in[11];
    const float* w_out    = (const float*)d_in[12];
    const float* ln2_g    = (const float*)d_in[13];
    const float* ln2_b    = (const float*)d_in[14];
    const float* fc1_w    = (const float*)d_in[15];
    const float* fc1_b    = (const float*)d_in[16];
    const float* fc2_w    = (const float*)d_in[17];
    const float* fc2_b    = (const float*)d_in[18];
    float* out = (float*)d_out;

    __half *h1, *xz, *u, *xdh, *dt, *g, *h2, *hid, *wr;
    float *x1, *ap, *hl, *h0;
    cudaGetSymbolAddress((void**)&h1,  g_h1);
    cudaGetSymbolAddress((void**)&xz,  g_xz);
    cudaGetSymbolAddress((void**)&u,   g_u);
    cudaGetSymbolAddress((void**)&xdh, g_xdh);
    cudaGetSymbolAddress((void**)&dt,  g_dt);
    cudaGetSymbolAddress((void**)&g,   g_g);
    cudaGetSymbolAddress((void**)&x1,  g_x1);
    cudaGetSymbolAddress((void**)&h2,  g_h2);
    cudaGetSymbolAddress((void**)&hid, g_hid);
    cudaGetSymbolAddress((void**)&wr,  g_wr);
    cudaGetSymbolAddress((void**)&ap,  g_ap);
    cudaGetSymbolAddress((void**)&hl,  g_hl);
    cudaGetSymbolAddress((void**)&h0,  g_h0);

    cudaFuncSetAttribute((void*)gemm_f16<0, __half, 128, 2, 4>, cudaFuncAttributeMaxDynamicSharedMemorySize, t5smem(128));
    cudaFuncSetAttribute((void*)gemm_f16<1, __half, 128, 2, 4>, cudaFuncAttributeMaxDynamicSharedMemorySize, t5smem(128));
    cudaFuncSetAttribute((void*)gemm_f16<4, __half, 128, 2, 4>, cudaFuncAttributeMaxDynamicSharedMemorySize, t5smem(128));
    cudaFuncSetAttribute((void*)gemm_f16<0, __half, 64, 4, 2>,  cudaFuncAttributeMaxDynamicSharedMemorySize, t5smem(64));
    cudaFuncSetAttribute((void*)gemm_f16<2, float, 64, 4, 2>,   cudaFuncAttributeMaxDynamicSharedMemorySize, t5smem(64));
    cudaFuncSetAttribute((void*)gemm_f16<3, float, 64, 4, 2>,   cudaFuncAttributeMaxDynamicSharedMemorySize, t5smem(64));
    cudaFuncSetAttribute((void*)scanC_kernel, cudaFuncAttributeMaxDynamicSharedMemorySize, SCANC_SMEM);

    // 0. weight prep: all 6 transforms in one launch
    prep_kernel<<<2112, 256>>>(w_in, w_out, fc1_w, fc2_w, x_proj_w, dt_w, wr);

    // 1. h1 = LN(x) -> fp16
    ln_kernel<<<NTOK / 8, 256>>>(x, ln1_g, ln1_b, h1, CDIM, 1e-6f);
    // 2. xz = h1 @ w_in
    gemm_f16<0, __half, 128, 2, 4><<<dim3(XZW / 128, NTOK / GBM), 256, t5smem(128)>>>(
        h1, wr + WR_WIN, xz, NTOK, XZW, CDIM, nullptr, nullptr);
    // 3. u = silu(dwconv3x3(xm))
    conv_silu_kernel<<<dim3(DI / 128, 32, NBAT), 256>>>(xz, conv_w, u);
    // 4. xd = u @ xprojT^T
    gemm_f16<0, __half, 64, 4, 2><<<dim3(1, NTOK / GBM), 256, t5smem(64)>>>(
        u, wr + WR_XP, xdh, NTOK, 64, DI, nullptr, nullptr);
    // 5. dt = softplus(xd @ dtwT^T + dtb)
    gemm_f16<4, __half, 128, 2, 4><<<dim3(DI / 128, NTOK / GBM), 256, t5smem(128)>>>(
        xdh, wr + WR_DTW, dt, NTOK, DI, 64, dt_b, nullptr);
    // 6. chunked scan: A (summaries), B (combine), C (apply + LN + gate, fused)
    scanA_kernel<<<NBAT * (DI / 32) * NCHUNK / 8, 256>>>(u, dt, xdh, A_log, ap, hl);
    scanB_kernel<<<NBAT * (DI / 32) / 8, 256>>>(ap, hl, h0);
    scanC_kernel<<<NBAT * NCHUNK, 768, SCANC_SMEM>>>(
        u, dt, xdh, A_log, Dp, h0, xz, on_g, on_b, g);
    // 7. x1 = g @ w_out + x
    gemm_f16<3, float, 64, 4, 2><<<dim3(CDIM / 64, NTOK / GBM), 256, t5smem(64)>>>(
        g, wr + WR_WOUT, x1, NTOK, CDIM, DI, nullptr, x);
    // 8. h2 = LN(x1) -> fp16
    ln_kernel<<<NTOK / 8, 256>>>(x1, ln2_g, ln2_b, h2, CDIM, 1e-6f);
    // 9. hid = gelu(h2 @ fc1_w + fc1_b) -> fp16
    gemm_f16<1, __half, 128, 2, 4><<<dim3(HIDD / 128, NTOK / GBM), 256, t5smem(128)>>>(
        h2, wr + WR_FC1, hid, NTOK, HIDD, CDIM, fc1_b, nullptr);
    // 10. out = hid @ fc2_w + fc2_b + x1
    gemm_f16<2, float, 64, 4, 2><<<dim3(CDIM / 64, NTOK / GBM), 256, t5smem(64)>>>(
        hid, wr + WR_FC2, out, NTOK, CDIM, HIDD, fc2_b, x1);
}